// round 8
// baseline (speedup 1.0000x reference)
#include <cuda_runtime.h>
#include <cuda_bf16.h>
#include <stdint.h>
#include <math.h>

// ---------------- problem constants ----------------
#define BB 2
#define LL 2048
#define HH 8
#define DMODEL 512
#define LEAF 4096

// ---------------- device scratch (static, no allocs) ----------------
__device__ float g_tree[8192 * 2 * 8 * 2 * 64];   // 64 MB  (node,b,h,k,d)
__device__ float g_u   [8192 * 2 * 8 * 2 * 64];   // 64 MB  u = W_s^T v on cover nodes
__device__ float g_qbase[BB * LL * DMODEL];       // 8 MB
__device__ float g_ctx[BB * LL * DMODEL];         // 8 MB

__device__ float4 g_gw[160][32];
__device__ float2 g_skw[64][32];
__device__ float  g_dv[13][32];
__device__ float  g_pr[13][8];
__device__ float  g_pi[13][8];
__device__ float  g_pq[13][2][64];
__device__ float  g_scale[13];
__device__ float  g_sigalpha;

// ---------------- helpers ----------------
__device__ __forceinline__ float wsum(float v) {
    v += __shfl_xor_sync(0xffffffffu, v, 16);
    v += __shfl_xor_sync(0xffffffffu, v, 8);
    v += __shfl_xor_sync(0xffffffffu, v, 4);
    v += __shfl_xor_sync(0xffffffffu, v, 2);
    v += __shfl_xor_sync(0xffffffffu, v, 1);
    return v;
}
__device__ __forceinline__ float sigf(float x) { return 1.0f / (1.0f + __expf(-x)); }

__device__ __forceinline__ void split2(float x, float y, unsigned int& hp, unsigned int& lp) {
    __nv_bfloat162 hh, ll;
    hh.x = __float2bfloat16(x);
    hh.y = __float2bfloat16(y);
    ll.x = __float2bfloat16(x - __bfloat162float(hh.x));
    ll.y = __float2bfloat16(y - __bfloat162float(hh.y));
    hp = *reinterpret_cast<unsigned int*>(&hh);
    lp = *reinterpret_cast<unsigned int*>(&ll);
}

__device__ __forceinline__ void mma_bf16(float* c, const unsigned int* a, const unsigned int* b) {
    asm volatile(
        "mma.sync.aligned.m16n8k16.row.col.f32.bf16.bf16.f32 "
        "{%0,%1,%2,%3}, {%4,%5,%6,%7}, {%8,%9}, {%0,%1,%2,%3};"
        : "+f"(c[0]), "+f"(c[1]), "+f"(c[2]), "+f"(c[3])
        : "r"(a[0]), "r"(a[1]), "r"(a[2]), "r"(a[3]), "r"(b[0]), "r"(b[1]));
}

// ---------------- precompute small tables ----------------
__global__ void precompute_kernel(
    const float* __restrict__ glw, const float* __restrict__ grw,
    const float* __restrict__ pqb, const float* __restrict__ qow,
    const float* __restrict__ qob, const float* __restrict__ skw,
    const float* __restrict__ salpha, const float* __restrict__ wfreq,
    const float* __restrict__ wdamp, const float* __restrict__ wphase,
    const float* __restrict__ dtemp)
{
    int t = threadIdx.x;  // 256 threads

    for (int idx = t; idx < 160 * 32; idx += 256) {
        int i = idx >> 5, l = idx & 31;
        g_gw[i][l] = make_float4(glw[l * 160 + i], glw[(l + 32) * 160 + i],
                                 grw[l * 160 + i], grw[(l + 32) * 160 + i]);
    }
    for (int idx = t; idx < 64 * 32; idx += 256) {
        int i = idx >> 5, l = idx & 31;
        g_skw[i][l] = make_float2(skw[l * 64 + i], skw[(l + 32) * 64 + i]);
    }
    for (int idx = t; idx < 13 * 32; idx += 256) {
        int d = idx >> 5, e = idx & 31;
        int i = e >> 1;
        float inv = expf(-(2.0f * (float)i) * logf(10000.0f) / 32.0f);
        float a = (float)d * inv;
        g_dv[d][e] = (e & 1) ? cosf(a) : sinf(a);
    }
    if (t < 13 * 8) {
        int d = t >> 3, h = t & 7;
        float sp = log1pf(expf(wdamp[h]));
        float decay = expf(-sp);
        float ang = wfreq[h] + wphase[h] + (float)d * 0.78539816339744831f;
        g_pr[d][h] = decay * cosf(ang);
        g_pi[d][h] = decay * sinf(ang);
    }
    if (t < 13) {
        float sp = log1pf(expf(dtemp[t]));
        g_scale[t] = 1.0f / ((sp + 1e-6f) * 8.0f);
    }
    if (t == 0) g_sigalpha = 1.0f / (1.0f + expf(-salpha[0]));

    __syncthreads();

    for (int idx = t; idx < 13 * 128; idx += 256) {
        int d = idx >> 7, kj = idx & 127;
        float s = pqb[kj] + qob[kj];
        for (int e = 0; e < 32; e++) s += qow[kj * 32 + e] * g_dv[d][e];
        g_pq[d][kj >> 6][kj & 63] = s;
    }
}

// ---------------- bf16-split tensor-core GEMM: C = A(4096x512) @ W(512x512)^T ----------------
template <int MODE, int ASRC>
__global__ void __launch_bounds__(256) gemm_bf16s(const float* __restrict__ A,
                                                  const float* __restrict__ W,
                                                  float* __restrict__ C)
{
    __shared__ unsigned int Ah[128][12], Al[128][12], Bh[128][12], Bl[128][12];
    const float* Ab = (ASRC == 0) ? A : g_ctx;
    int t = threadIdx.x;
    int lane = t & 31, wid = t >> 5;
    int wm = (wid & 1) * 64, wn = (wid >> 1) * 32;
    int m0 = blockIdx.x * 128, n0 = blockIdx.y * 128;
    int g = lane >> 2, tq = lane & 3;

    float c[4][4][4];
#pragma unroll
    for (int i = 0; i < 4; i++)
#pragma unroll
        for (int j = 0; j < 4; j++)
#pragma unroll
            for (int k = 0; k < 4; k++) c[i][j][k] = 0.0f;

    for (int k0 = 0; k0 < DMODEL; k0 += 16) {
#pragma unroll
        for (int j = 0; j < 2; j++) {
            int q = t + 256 * j;
            int row = q >> 2, kq = q & 3;
            float4 va = *(const float4*)(Ab + (size_t)(m0 + row) * DMODEL + k0 + kq * 4);
            unsigned int hp, lp;
            split2(va.x, va.y, hp, lp); Ah[row][kq * 2] = hp;     Al[row][kq * 2] = lp;
            split2(va.z, va.w, hp, lp); Ah[row][kq * 2 + 1] = hp; Al[row][kq * 2 + 1] = lp;
            float4 vb = *(const float4*)(W + (size_t)(n0 + row) * DMODEL + k0 + kq * 4);
            split2(vb.x, vb.y, hp, lp); Bh[row][kq * 2] = hp;     Bl[row][kq * 2] = lp;
            split2(vb.z, vb.w, hp, lp); Bh[row][kq * 2 + 1] = hp; Bl[row][kq * 2 + 1] = lp;
        }
        __syncthreads();

        unsigned int ah[4][4], al[4][4], bh[4][2], bl[4][2];
#pragma unroll
        for (int mt = 0; mt < 4; mt++) {
            int r = wm + mt * 16 + g;
            ah[mt][0] = Ah[r][tq];     ah[mt][1] = Ah[r + 8][tq];
            ah[mt][2] = Ah[r][tq + 4]; ah[mt][3] = Ah[r + 8][tq + 4];
            al[mt][0] = Al[r][tq];     al[mt][1] = Al[r + 8][tq];
            al[mt][2] = Al[r][tq + 4]; al[mt][3] = Al[r + 8][tq + 4];
        }
#pragma unroll
        for (int nt = 0; nt < 4; nt++) {
            int n = wn + nt * 8 + g;
            bh[nt][0] = Bh[n][tq]; bh[nt][1] = Bh[n][tq + 4];
            bl[nt][0] = Bl[n][tq]; bl[nt][1] = Bl[n][tq + 4];
        }
#pragma unroll
        for (int mt = 0; mt < 4; mt++)
#pragma unroll
            for (int nt = 0; nt < 4; nt++) {
                mma_bf16(c[mt][nt], ah[mt], bh[nt]);
                mma_bf16(c[mt][nt], al[mt], bh[nt]);
                mma_bf16(c[mt][nt], ah[mt], bl[nt]);
            }
        __syncthreads();
    }

#pragma unroll
    for (int mt = 0; mt < 4; mt++)
#pragma unroll
        for (int nt = 0; nt < 4; nt++) {
            int r0 = m0 + wm + mt * 16 + g;
            int cc = n0 + wn + nt * 8 + tq * 2;
            float2 v0 = make_float2(c[mt][nt][0], c[mt][nt][1]);
            float2 v1 = make_float2(c[mt][nt][2], c[mt][nt][3]);
            if (MODE == 0) {
                *(float2*)(C + (size_t)r0 * DMODEL + cc) = v0;
                *(float2*)(C + (size_t)(r0 + 8) * DMODEL + cc) = v1;
            } else if (MODE == 2) {
                *(float2*)(g_qbase + (size_t)r0 * DMODEL + cc) = v0;
                *(float2*)(g_qbase + (size_t)(r0 + 8) * DMODEL + cc) = v1;
            } else {
                int hh = cc >> 6, dd = cc & 63;
                int b0 = r0 >> 11, l0 = r0 & 2047;
                *(float2*)(g_tree + ((size_t)(((LEAF + l0) * 2 + b0) * 8 + hh)) * 128 + dd) = v0;
                int r1 = r0 + 8;
                int b1 = r1 >> 11, l1 = r1 & 2047;
                *(float2*)(g_tree + ((size_t)(((LEAF + l1) * 2 + b1) * 8 + hh)) * 128 + dd) = v1;
            }
        }
}

// ---------------- tree merge: one warp per (NPW nodes, h), both b fused ----------------
// Per-instance math identical to round-5-verified kernel; NPW adds an outer j loop
// so each g_gw fetch (512B/warp through L1) feeds 8*NPW FMAs instead of 8.
template <int KC, int NPW>
__global__ void __launch_bounds__(256) merge_kernel(int d, int lo,
                             const float* __restrict__ glb, const float* __restrict__ grb,
                             const float* __restrict__ ln_g, const float* __restrict__ ln_b)
{
    constexpr int NS = 2 * KC;
    __shared__ float s_gin[8][NPW][2][160];
    int warp = threadIdx.x >> 5;
    int lane = threadIdx.x & 31;
    int inst = blockIdx.x * 8 + warp;          // (nodeGroup)*8 + h
    int ngroups = lo / NPW;
    if (inst >= ngroups * 8) return;
    int node0 = lo + (inst >> 3) * NPW;
    int h = inst & 7;

    float pr = g_pr[d][h], pi = g_pi[d][h];
    float dvl = g_dv[d][lane];

    float fla[NPW][2][KC], flb[NPW][2][KC], rta[NPW][2][KC], rtb[NPW][2][KC];
#pragma unroll
    for (int j = 0; j < NPW; j++) {
        int node = node0 + j;
#pragma unroll
        for (int b = 0; b < 2; b++) {
            const float* tl = g_tree + (size_t)(((2 * node) * 2 + b) * 8 + h) * 128;
            const float* tr = g_tree + (size_t)(((2 * node + 1) * 2 + b) * 8 + h) * 128;
#pragma unroll
            for (int k = 0; k < KC; k++) {
                fla[j][b][k] = tl[k * 64 + lane];
                flb[j][b][k] = tl[k * 64 + lane + 32];
                float fr = tr[k * 64 + lane];
                float fi = tr[k * 64 + lane + 32];
                rta[j][b][k] = pr * fr - pi * fi;
                rtb[j][b][k] = pi * fr + pr * fi;
            }
            float lma, lmb, rma, rmb;
            if (KC == 2) {
                lma = 0.5f * (fla[j][b][0] + fla[j][b][1]); lmb = 0.5f * (flb[j][b][0] + flb[j][b][1]);
                rma = 0.5f * (rta[j][b][0] + rta[j][b][1]); rmb = 0.5f * (rtb[j][b][0] + rtb[j][b][1]);
            } else {
                lma = fla[j][b][0]; lmb = flb[j][b][0]; rma = rta[j][b][0]; rmb = rtb[j][b][0];
            }
            float* gin = s_gin[warp][j][b];
            gin[lane] = lma; gin[lane + 32] = lmb;
            gin[64 + lane] = rma; gin[96 + lane] = rmb;
            gin[128 + lane] = dvl;
        }
    }
    __syncwarp();

    float al0[NPW][2], al1[NPW][2], ar0[NPW][2], ar1[NPW][2];
    {
        float bl0 = glb[lane], bl1 = glb[lane + 32];
        float br0 = grb[lane], br1 = grb[lane + 32];
#pragma unroll
        for (int j = 0; j < NPW; j++)
#pragma unroll
            for (int b = 0; b < 2; b++) {
                al0[j][b] = bl0; al1[j][b] = bl1;
                ar0[j][b] = br0; ar1[j][b] = br1;
            }
    }
#pragma unroll 2
    for (int i = 0; i < 160; i++) {
        float4 w = g_gw[i][lane];
#pragma unroll
        for (int j = 0; j < NPW; j++)
#pragma unroll
            for (int b = 0; b < 2; b++) {
                float gi = s_gin[warp][j][b][i];
                al0[j][b] = fmaf(w.x, gi, al0[j][b]); al1[j][b] = fmaf(w.y, gi, al1[j][b]);
                ar0[j][b] = fmaf(w.z, gi, ar0[j][b]); ar1[j][b] = fmaf(w.w, gi, ar1[j][b]);
            }
    }

    float ska[NPW][2], skb[NPW][2];
#pragma unroll
    for (int j = 0; j < NPW; j++)
#pragma unroll
        for (int b = 0; b < 2; b++) { ska[j][b] = 0.0f; skb[j][b] = 0.0f; }
#pragma unroll 2
    for (int i = 0; i < 64; i++) {
        float2 w = g_skw[i][lane];
#pragma unroll
        for (int j = 0; j < NPW; j++)
#pragma unroll
            for (int b = 0; b < 2; b++) {
                float l = s_gin[warp][j][b][i];
                ska[j][b] = fmaf(w.x, l, ska[j][b]);
                skb[j][b] = fmaf(w.y, l, skb[j][b]);
            }
    }

    float sa = g_sigalpha;
    float gma = ln_g[lane], gmb = ln_g[lane + 32];
    float bta = ln_b[lane], btb = ln_b[lane + 32];

#pragma unroll
    for (int j = 0; j < NPW; j++) {
        int node = node0 + j;
#pragma unroll
        for (int b = 0; b < 2; b++) {
            float gla = sigf(al0[j][b]), glv = sigf(al1[j][b]);
            float gra = sigf(ar0[j][b]), grv = sigf(ar1[j][b]);

            float bka[NS], bkb[NS];
#pragma unroll
            for (int k = 0; k < KC; k++) {
                bka[k] = fla[j][b][k] * gla;      bkb[k] = flb[j][b][k] * glv;
                bka[KC + k] = rta[j][b][k] * gra; bkb[KC + k] = rtb[j][b][k] * grv;
            }
            size_t obase = (size_t)((node * 2 + b) * 8 + h) * 128;

#pragma unroll
            for (int q = 0; q < 2; q++) {
                float pqa = g_pq[d][q][lane], pqb = g_pq[d][q][lane + 32];
                float sc[NS];
#pragma unroll
                for (int s = 0; s < NS; s++) {
                    float p = pqa * bka[s] + pqb * bkb[s];
                    sc[s] = wsum(p) * 0.125f;
                }
                float mx = sc[0];
#pragma unroll
                for (int s = 1; s < NS; s++) mx = fmaxf(mx, sc[s]);
                float den = 0.0f;
#pragma unroll
                for (int s = 0; s < NS; s++) { sc[s] = __expf(sc[s] - mx); den += sc[s]; }
                float inv = 1.0f / den;
                float ra = 0.0f, rb = 0.0f;
#pragma unroll
                for (int s = 0; s < NS; s++) {
                    float w = sc[s] * inv;
                    ra = fmaf(w, bka[s], ra);
                    rb = fmaf(w, bkb[s], rb);
                }
                float mu = wsum(ra + rb) * (1.0f / 64.0f);
                float da = ra - mu, db = rb - mu;
                float var = wsum(da * da + db * db) * (1.0f / 64.0f);
                float rstd = rsqrtf(var + 1e-5f);
                g_tree[obase + q * 64 + lane]      = da * rstd * gma + bta + sa * ska[j][b];
                g_tree[obase + q * 64 + lane + 32] = db * rstd * gmb + btb + sa * skb[j][b];
            }
        }
    }
}

// ---------------- u = W_s^T v for the 2048 cover-reachable (node,depth) entries ----------------
__global__ void utransform_kernel(const float* __restrict__ dpw)
{
    __shared__ float sv[8][4][64];
    int e = blockIdx.x;                    // 0..2047
    int h = threadIdx.x >> 5, lane = threadIdx.x & 31;

    int s = 0, base = 0;
#pragma unroll
    for (int ss = 0; ss < 12; ss++) {
        int cnt = 1024 >> ss; if (cnt == 0) cnt = 1;
        if (e >= base + cnt) { base += cnt; s = ss + 1; }
        else break;
    }
    int node = (1 << (12 - s)) + 2 * (e - base);
    int kv = (s == 0) ? 1 : 2;
    int nvec = 2 * kv;
    const float* W = dpw + (size_t)s * 4096;

    for (int j = 0; j < nvec; j++) {
        int b = j / kv, k = j % kv;
        const float* src = g_tree + (size_t)((node * 2 + b) * 8 + h) * 128 + k * 64;
        sv[h][j][lane] = src[lane];
        sv[h][j][lane + 32] = src[lane + 32];
    }
    __syncwarp();

    float u0[4] = {0, 0, 0, 0}, u1[4] = {0, 0, 0, 0};
    for (int o = 0; o < 64; o++) {
        float w0 = W[o * 64 + lane];
        float w1 = W[o * 64 + lane + 32];
#pragma unroll
        for (int j = 0; j < 4; j++) {
            if (j < nvec) {
                float v = sv[h][j][o];
                u0[j] = fmaf(w0, v, u0[j]);
                u1[j] = fmaf(w1, v, u1[j]);
            }
        }
    }
    for (int j = 0; j < nvec; j++) {
        int b = j / kv, k = j % kv;
        float* dst = g_u + (size_t)((node * 2 + b) * 8 + h) * 128 + k * 64;
        dst[lane] = u0[j];
        dst[lane + 32] = u1[j];
    }
}

// ---------------- cover attention: one warp per (t,b,h), scores use q.(v+u) ----------------
__global__ void cover_attn_kernel()
{
    int t = blockIdx.x, b = blockIdx.y;
    int h = threadIdx.x >> 5, lane = threadIdx.x & 31;
    int pos = t + 1;
    const float* qp = g_qbase + (size_t)(b * LL + t) * DMODEL + h * 64;
    float qa = qp[lane], qb = qp[lane + 32];

    float m = -1e30f, den = 0.0f, ca = 0.0f, cb = 0.0f;
#pragma unroll
    for (int s = 0; s < 12; s++) {
        if ((pos >> s) & 1) {
            int node = ((LEAF + pos) >> s) - 1;
            float scl = g_scale[s];
            size_t off = (size_t)((node * 2 + b) * 8 + h) * 128;
            int kv = (s == 0) ? 1 : 2;
            for (int k = 0; k < kv; k++) {
                float va = g_tree[off + k * 64 + lane];
                float vb = g_tree[off + k * 64 + lane + 32];
                float ua = g_u[off + k * 64 + lane];
                float ub = g_u[off + k * 64 + lane + 32];
                float dot = wsum(qa * (va + ua) + qb * (vb + ub)) * scl;
                float nm = fmaxf(m, dot);
                float f = __expf(m - nm);
                float e = __expf(dot - nm);
                den = den * f + e;
                ca = ca * f + e * va;
                cb = cb * f + e * vb;
                m = nm;
            }
        }
    }
    float inv = 1.0f / den;
    size_t o = (size_t)(b * LL + t) * DMODEL + h * 64;
    g_ctx[o + lane] = ca * inv;
    g_ctx[o + lane + 32] = cb * inv;
}

// ---------------- launcher ----------------
extern "C" void kernel_launch(void* const* d_in, const int* in_sizes, int n_in,
                              void* d_out, int out_size)
{
    const float* x      = (const float*)d_in[0];
    const float* Wq     = (const float*)d_in[1];
    const float* Wv     = (const float*)d_in[2];
    const float* Wo     = (const float*)d_in[3];
    const float* glw    = (const float*)d_in[4];
    const float* glb    = (const float*)d_in[5];
    const float* grw    = (const float*)d_in[6];
    const float* grb    = (const float*)d_in[7];
    const float* pqb    = (const float*)d_in[8];
    const float* qow    = (const float*)d_in[9];
    const float* qob    = (const float*)d_in[10];
    const float* lng    = (const float*)d_in[11];
    const float* lnb    = (const float*)d_in[12];
    const float* skw    = (const float*)d_in[13];
    const float* salpha = (const float*)d_in[14];
    const float* wfreq  = (const float*)d_in[15];
    const float* wdamp  = (const float*)d_in[16];
    const float* wphase = (const float*)d_in[17];
    const float* dpw    = (const float*)d_in[18];
    const float* dtemp  = (const float*)d_in[19];

    precompute_kernel<<<1, 256>>>(glw, grw, pqb, qow, qob, skw, salpha,
                                  wfreq, wdamp, wphase, dtemp);

    // q_base = x @ Wq^T ; v -> tree leaves = x @ Wv^T   (bf16-split tensor cores)
    gemm_bf16s<2, 0><<<dim3(32, 4), 256>>>(x, Wq, nullptr);
    gemm_bf16s<1, 0><<<dim3(32, 4), 256>>>(x, Wv, nullptr);

    // tree merges, levels 1..11 (root unused by covers)
    for (int d = 1; d <= 11; d++) {
        int lo = 1 << (12 - d);
        if (d == 1) {
            merge_kernel<1, 4><<<lo / 4, 256>>>(d, lo, glb, grb, lng, lnb);
        } else if (lo >= 64) {
            merge_kernel<2, 2><<<lo / 2, 256>>>(d, lo, glb, grb, lng, lnb);
        } else {
            merge_kernel<2, 1><<<lo, 256>>>(d, lo, glb, grb, lng, lnb);
        }
    }

    // u = W_s^T v on cover-reachable nodes
    utransform_kernel<<<2048, 256>>>(dpw);

    // cover attention -> ctx
    cover_attn_kernel<<<dim3(LL, BB), 256>>>();

    // out = ctx @ Wo^T
    gemm_bf16s<0, 1><<<dim3(32, 4), 256>>>(nullptr, Wo, (float*)d_out);
}

// round 11
// speedup vs baseline: 1.0704x; 1.0704x over previous
#include <cuda_runtime.h>
#include <cuda_bf16.h>
#include <stdint.h>
#include <math.h>

// ---------------- problem constants ----------------
#define BB 2
#define LL 2048
#define HH 8
#define DMODEL 512
#define LEAF 4096

// ---------------- device scratch (static, no allocs) ----------------
__device__ float g_tree[8192 * 2 * 8 * 2 * 64];   // 64 MB  (node,b,h,k,d)
__device__ float g_u   [8192 * 2 * 8 * 2 * 64];   // 64 MB
__device__ float g_qbase[BB * LL * DMODEL];       // 8 MB
__device__ float g_ctx[BB * LL * DMODEL];         // 8 MB
__device__ float g_gin [32768 * 160];             // 21 MB  gate_in rows (big levels)
__device__ float g_gout[32768 * 192];             // 25 MB  gate GEMM output

__device__ float4 g_gw[160][32];
__device__ float2 g_skw[64][32];
__device__ unsigned int g_wgh[192][80];           // combined gate+skip weights, bf16-hi packed x2
__device__ unsigned int g_wgl[192][80];           // bf16-lo residual
__device__ float  g_dv[13][32];
__device__ float  g_pr[13][8];
__device__ float  g_pi[13][8];
__device__ float  g_pq[13][2][64];
__device__ float  g_scale[13];
__device__ float  g_sigalpha;

// ---------------- helpers ----------------
__device__ __forceinline__ float wsum(float v) {
    v += __shfl_xor_sync(0xffffffffu, v, 16);
    v += __shfl_xor_sync(0xffffffffu, v, 8);
    v += __shfl_xor_sync(0xffffffffu, v, 4);
    v += __shfl_xor_sync(0xffffffffu, v, 2);
    v += __shfl_xor_sync(0xffffffffu, v, 1);
    return v;
}
__device__ __forceinline__ float sigf(float x) { return 1.0f / (1.0f + __expf(-x)); }

__device__ __forceinline__ void split2(float x, float y, unsigned int& hp, unsigned int& lp) {
    __nv_bfloat162 hh, ll;
    hh.x = __float2bfloat16(x);
    hh.y = __float2bfloat16(y);
    ll.x = __float2bfloat16(x - __bfloat162float(hh.x));
    ll.y = __float2bfloat16(y - __bfloat162float(hh.y));
    hp = *reinterpret_cast<unsigned int*>(&hh);
    lp = *reinterpret_cast<unsigned int*>(&ll);
}

__device__ __forceinline__ void mma_bf16(float* c, const unsigned int* a, const unsigned int* b) {
    asm volatile(
        "mma.sync.aligned.m16n8k16.row.col.f32.bf16.bf16.f32 "
        "{%0,%1,%2,%3}, {%4,%5,%6,%7}, {%8,%9}, {%0,%1,%2,%3};"
        : "+f"(c[0]), "+f"(c[1]), "+f"(c[2]), "+f"(c[3])
        : "r"(a[0]), "r"(a[1]), "r"(a[2]), "r"(a[3]), "r"(b[0]), "r"(b[1]));
}

__device__ __forceinline__ float fetch_wg(const float* glw, const float* grw,
                                          const float* skw, int r, int k) {
    if (r < 64) return glw[r * 160 + k];
    if (r < 128) return grw[(r - 64) * 160 + k];
    return (k < 64) ? skw[(r - 128) * 64 + k] : 0.0f;
}

// ---------------- precompute small tables ----------------
__global__ void precompute_kernel(
    const float* __restrict__ glw, const float* __restrict__ grw,
    const float* __restrict__ pqb, const float* __restrict__ qow,
    const float* __restrict__ qob, const float* __restrict__ skw,
    const float* __restrict__ salpha, const float* __restrict__ wfreq,
    const float* __restrict__ wdamp, const float* __restrict__ wphase,
    const float* __restrict__ dtemp)
{
    int t = threadIdx.x;  // 256 threads

    for (int idx = t; idx < 160 * 32; idx += 256) {
        int i = idx >> 5, l = idx & 31;
        g_gw[i][l] = make_float4(glw[l * 160 + i], glw[(l + 32) * 160 + i],
                                 grw[l * 160 + i], grw[(l + 32) * 160 + i]);
    }
    for (int idx = t; idx < 64 * 32; idx += 256) {
        int i = idx >> 5, l = idx & 31;
        g_skw[i][l] = make_float2(skw[l * 64 + i], skw[(l + 32) * 64 + i]);
    }
    // combined gate/skip weight, bf16-split, packed pairs along k
    for (int idx = t; idx < 192 * 80; idx += 256) {
        int r = idx / 80, kp = idx % 80;
        float v0 = fetch_wg(glw, grw, skw, r, kp * 2);
        float v1 = fetch_wg(glw, grw, skw, r, kp * 2 + 1);
        unsigned int hp, lp;
        split2(v0, v1, hp, lp);
        g_wgh[r][kp] = hp;
        g_wgl[r][kp] = lp;
    }
    for (int idx = t; idx < 13 * 32; idx += 256) {
        int d = idx >> 5, e = idx & 31;
        int i = e >> 1;
        float inv = expf(-(2.0f * (float)i) * logf(10000.0f) / 32.0f);
        float a = (float)d * inv;
        g_dv[d][e] = (e & 1) ? cosf(a) : sinf(a);
    }
    if (t < 13 * 8) {
        int d = t >> 3, h = t & 7;
        float sp = log1pf(expf(wdamp[h]));
        float decay = expf(-sp);
        float ang = wfreq[h] + wphase[h] + (float)d * 0.78539816339744831f;
        g_pr[d][h] = decay * cosf(ang);
        g_pi[d][h] = decay * sinf(ang);
    }
    if (t < 13) {
        float sp = log1pf(expf(dtemp[t]));
        g_scale[t] = 1.0f / ((sp + 1e-6f) * 8.0f);
    }
    if (t == 0) g_sigalpha = 1.0f / (1.0f + expf(-salpha[0]));

    __syncthreads();

    for (int idx = t; idx < 13 * 128; idx += 256) {
        int d = idx >> 7, kj = idx & 127;
        float s = pqb[kj] + qob[kj];
        for (int e = 0; e < 32; e++) s += qow[kj * 32 + e] * g_dv[d][e];
        g_pq[d][kj >> 6][kj & 63] = s;
    }
}

// ---------------- bf16-split tensor-core GEMM: C = A(4096x512) @ W(512x512)^T ----------------
template <int MODE, int ASRC>
__global__ void __launch_bounds__(256) gemm_bf16s(const float* __restrict__ A,
                                                  const float* __restrict__ W,
                                                  float* __restrict__ C)
{
    __shared__ unsigned int Ah[128][12], Al[128][12], Bh[128][12], Bl[128][12];
    const float* Ab = (ASRC == 0) ? A : g_ctx;
    int t = threadIdx.x;
    int lane = t & 31, wid = t >> 5;
    int wm = (wid & 1) * 64, wn = (wid >> 1) * 32;
    int m0 = blockIdx.x * 128, n0 = blockIdx.y * 128;
    int g = lane >> 2, tq = lane & 3;

    float c[4][4][4];
#pragma unroll
    for (int i = 0; i < 4; i++)
#pragma unroll
        for (int j = 0; j < 4; j++)
#pragma unroll
            for (int k = 0; k < 4; k++) c[i][j][k] = 0.0f;

    for (int k0 = 0; k0 < DMODEL; k0 += 16) {
#pragma unroll
        for (int j = 0; j < 2; j++) {
            int q = t + 256 * j;
            int row = q >> 2, kq = q & 3;
            float4 va = *(const float4*)(Ab + (size_t)(m0 + row) * DMODEL + k0 + kq * 4);
            unsigned int hp, lp;
            split2(va.x, va.y, hp, lp); Ah[row][kq * 2] = hp;     Al[row][kq * 2] = lp;
            split2(va.z, va.w, hp, lp); Ah[row][kq * 2 + 1] = hp; Al[row][kq * 2 + 1] = lp;
            float4 vb = *(const float4*)(W + (size_t)(n0 + row) * DMODEL + k0 + kq * 4);
            split2(vb.x, vb.y, hp, lp); Bh[row][kq * 2] = hp;     Bl[row][kq * 2] = lp;
            split2(vb.z, vb.w, hp, lp); Bh[row][kq * 2 + 1] = hp; Bl[row][kq * 2 + 1] = lp;
        }
        __syncthreads();

        unsigned int ah[4][4], al[4][4], bh[4][2], bl[4][2];
#pragma unroll
        for (int mt = 0; mt < 4; mt++) {
            int r = wm + mt * 16 + g;
            ah[mt][0] = Ah[r][tq];     ah[mt][1] = Ah[r + 8][tq];
            ah[mt][2] = Ah[r][tq + 4]; ah[mt][3] = Ah[r + 8][tq + 4];
            al[mt][0] = Al[r][tq];     al[mt][1] = Al[r + 8][tq];
            al[mt][2] = Al[r][tq + 4]; al[mt][3] = Al[r + 8][tq + 4];
        }
#pragma unroll
        for (int nt = 0; nt < 4; nt++) {
            int n = wn + nt * 8 + g;
            bh[nt][0] = Bh[n][tq]; bh[nt][1] = Bh[n][tq + 4];
            bl[nt][0] = Bl[n][tq]; bl[nt][1] = Bl[n][tq + 4];
        }
#pragma unroll
        for (int mt = 0; mt < 4; mt++)
#pragma unroll
            for (int nt = 0; nt < 4; nt++) {
                mma_bf16(c[mt][nt], ah[mt], bh[nt]);
                mma_bf16(c[mt][nt], al[mt], bh[nt]);
                mma_bf16(c[mt][nt], ah[mt], bl[nt]);
            }
        __syncthreads();
    }

#pragma unroll
    for (int mt = 0; mt < 4; mt++)
#pragma unroll
        for (int nt = 0; nt < 4; nt++) {
            int r0 = m0 + wm + mt * 16 + g;
            int cc = n0 + wn + nt * 8 + tq * 2;
            float2 v0 = make_float2(c[mt][nt][0], c[mt][nt][1]);
            float2 v1 = make_float2(c[mt][nt][2], c[mt][nt][3]);
            if (MODE == 0) {
                *(float2*)(C + (size_t)r0 * DMODEL + cc) = v0;
                *(float2*)(C + (size_t)(r0 + 8) * DMODEL + cc) = v1;
            } else if (MODE == 2) {
                *(float2*)(g_qbase + (size_t)r0 * DMODEL + cc) = v0;
                *(float2*)(g_qbase + (size_t)(r0 + 8) * DMODEL + cc) = v1;
            } else {
                int hh = cc >> 6, dd = cc & 63;
                int b0 = r0 >> 11, l0 = r0 & 2047;
                *(float2*)(g_tree + ((size_t)(((LEAF + l0) * 2 + b0) * 8 + hh)) * 128 + dd) = v0;
                int r1 = r0 + 8;
                int b1 = r1 >> 11, l1 = r1 & 2047;
                *(float2*)(g_tree + ((size_t)(((LEAF + l1) * 2 + b1) * 8 + hh)) * 128 + dd) = v1;
            }
        }
}

// ---------------- big-level merge, stage 1: build gate_in rows ----------------
// inst = ((node-lo)*2 + b)*8 + h ; row layout: [lm(64) | rm(64) | dv(32)]
template <int KC>
__global__ void __launch_bounds__(256) merge_prep(int d, int lo)
{
    int warp = threadIdx.x >> 5, lane = threadIdx.x & 31;
    int inst = blockIdx.x * 8 + warp;
    if (inst >= lo * 16) return;
    int node = lo + (inst >> 4);
    int b = (inst >> 3) & 1;
    int h = inst & 7;

    float pr = g_pr[d][h], pi = g_pi[d][h];
    const float* tl = g_tree + (size_t)(((2 * node) * 2 + b) * 8 + h) * 128;
    const float* tr = g_tree + (size_t)(((2 * node + 1) * 2 + b) * 8 + h) * 128;

    float fla[KC], flb[KC], rta[KC], rtb[KC];
#pragma unroll
    for (int k = 0; k < KC; k++) {
        fla[k] = tl[k * 64 + lane];
        flb[k] = tl[k * 64 + lane + 32];
        float fr = tr[k * 64 + lane];
        float fi = tr[k * 64 + lane + 32];
        rta[k] = pr * fr - pi * fi;
        rtb[k] = pi * fr + pr * fi;
    }
    float lma, lmb, rma, rmb;
    if (KC == 2) {
        lma = 0.5f * (fla[0] + fla[1]); lmb = 0.5f * (flb[0] + flb[1]);
        rma = 0.5f * (rta[0] + rta[1]); rmb = 0.5f * (rtb[0] + rtb[1]);
    } else {
        lma = fla[0]; lmb = flb[0]; rma = rta[0]; rmb = rtb[0];
    }
    float* row = g_gin + (size_t)inst * 160;
    row[lane] = lma; row[lane + 32] = lmb;
    row[64 + lane] = rma; row[96 + lane] = rmb;
    row[128 + lane] = g_dv[d][lane];
}

// ---------------- big-level merge, stage 2: gate GEMM (M x 160) @ (192 x 160)^T ----------------
// grid = (M/128, 3); out cols: [0,64) gate_left, [64,128) gate_right, [128,192) skip
__global__ void __launch_bounds__(256) gate_gemm(int M)
{
    __shared__ unsigned int Ah[128][12], Al[128][12], Bh[64][12], Bl[64][12];
    int t = threadIdx.x;
    int lane = t & 31, wid = t >> 5;
    int m0 = blockIdx.x * 128, n0 = blockIdx.y * 64;
    int wm = wid * 16;
    int g = lane >> 2, tq = lane & 3;

    float c[8][4];
#pragma unroll
    for (int i = 0; i < 8; i++)
#pragma unroll
        for (int j = 0; j < 4; j++) c[i][j] = 0.0f;

    for (int chunk = 0; chunk < 10; chunk++) {
        int k0 = chunk * 16;
#pragma unroll
        for (int j = 0; j < 2; j++) {
            int q = t + 256 * j;
            int row = q >> 2, kq = q & 3;
            float4 va = *(const float4*)(g_gin + (size_t)(m0 + row) * 160 + k0 + kq * 4);
            unsigned int hp, lp;
            split2(va.x, va.y, hp, lp); Ah[row][kq * 2] = hp;     Al[row][kq * 2] = lp;
            split2(va.z, va.w, hp, lp); Ah[row][kq * 2 + 1] = hp; Al[row][kq * 2 + 1] = lp;
        }
        // FIXED (round-9 NaN): 512 B-tile entries, 256 threads -> strided loop
        for (int q = t; q < 512; q += 256) {
            int row = q >> 3, cc = q & 7;
            Bh[row][cc] = g_wgh[n0 + row][chunk * 8 + cc];
            Bl[row][cc] = g_wgl[n0 + row][chunk * 8 + cc];
        }
        __syncthreads();

        unsigned int ah[4], al[4];
        int r = wm + g;
        ah[0] = Ah[r][tq];     ah[1] = Ah[r + 8][tq];
        ah[2] = Ah[r][tq + 4]; ah[3] = Ah[r + 8][tq + 4];
        al[0] = Al[r][tq];     al[1] = Al[r + 8][tq];
        al[2] = Al[r][tq + 4]; al[3] = Al[r + 8][tq + 4];
#pragma unroll
        for (int nt = 0; nt < 8; nt++) {
            int n = nt * 8 + g;
            unsigned int bh[2] = {Bh[n][tq], Bh[n][tq + 4]};
            unsigned int bl[2] = {Bl[n][tq], Bl[n][tq + 4]};
            mma_bf16(c[nt], ah, bh);
            mma_bf16(c[nt], al, bh);
            mma_bf16(c[nt], ah, bl);
        }
        __syncthreads();
    }

#pragma unroll
    for (int nt = 0; nt < 8; nt++) {
        int r0 = m0 + wm + g;
        int cc = n0 + nt * 8 + tq * 2;
        *(float2*)(g_gout + (size_t)r0 * 192 + cc) = make_float2(c[nt][0], c[nt][1]);
        *(float2*)(g_gout + (size_t)(r0 + 8) * 192 + cc) = make_float2(c[nt][2], c[nt][3]);
    }
}

// ---------------- big-level merge, stage 3: epilogue (verified round-7 math) ----------------
template <int KC>
__global__ void __launch_bounds__(256) merge_epi(int d, int lo,
                             const float* __restrict__ glb, const float* __restrict__ grb,
                             const float* __restrict__ ln_g, const float* __restrict__ ln_b)
{
    constexpr int NS = 2 * KC;
    int warp = threadIdx.x >> 5, lane = threadIdx.x & 31;
    int inst = blockIdx.x * 8 + warp;
    if (inst >= lo * 16) return;
    int node = lo + (inst >> 4);
    int b = (inst >> 3) & 1;
    int h = inst & 7;

    float pr = g_pr[d][h], pi = g_pi[d][h];
    const float* tl = g_tree + (size_t)(((2 * node) * 2 + b) * 8 + h) * 128;
    const float* tr = g_tree + (size_t)(((2 * node + 1) * 2 + b) * 8 + h) * 128;

    float fla[KC], flb[KC], rta[KC], rtb[KC];
#pragma unroll
    for (int k = 0; k < KC; k++) {
        fla[k] = tl[k * 64 + lane];
        flb[k] = tl[k * 64 + lane + 32];
        float fr = tr[k * 64 + lane];
        float fi = tr[k * 64 + lane + 32];
        rta[k] = pr * fr - pi * fi;
        rtb[k] = pi * fr + pr * fi;
    }

    const float* go = g_gout + (size_t)inst * 192;
    float gla = sigf(go[lane] + glb[lane]);
    float glv = sigf(go[lane + 32] + glb[lane + 32]);
    float gra = sigf(go[64 + lane] + grb[lane]);
    float grv = sigf(go[96 + lane] + grb[lane + 32]);
    float ska = go[128 + lane];
    float skb = go[160 + lane];

    float bka[NS], bkb[NS];
#pragma unroll
    for (int k = 0; k < KC; k++) {
        bka[k] = fla[k] * gla;      bkb[k] = flb[k] * glv;
        bka[KC + k] = rta[k] * gra; bkb[KC + k] = rtb[k] * grv;
    }

    float sa = g_sigalpha;
    float gma = ln_g[lane], gmb = ln_g[lane + 32];
    float bta = ln_b[lane], btb = ln_b[lane + 32];
    size_t obase = (size_t)((node * 2 + b) * 8 + h) * 128;

#pragma unroll
    for (int q = 0; q < 2; q++) {
        float pqa = g_pq[d][q][lane], pqb = g_pq[d][q][lane + 32];
        float sc[NS];
#pragma unroll
        for (int s = 0; s < NS; s++) {
            float p = pqa * bka[s] + pqb * bkb[s];
            sc[s] = wsum(p) * 0.125f;
        }
        float mx = sc[0];
#pragma unroll
        for (int s = 1; s < NS; s++) mx = fmaxf(mx, sc[s]);
        float den = 0.0f;
#pragma unroll
        for (int s = 0; s < NS; s++) { sc[s] = __expf(sc[s] - mx); den += sc[s]; }
        float inv = 1.0f / den;
        float ra = 0.0f, rb = 0.0f;
#pragma unroll
        for (int s = 0; s < NS; s++) {
            float w = sc[s] * inv;
            ra = fmaf(w, bka[s], ra);
            rb = fmaf(w, bkb[s], rb);
        }
        float mu = wsum(ra + rb) * (1.0f / 64.0f);
        float da = ra - mu, db = rb - mu;
        float var = wsum(da * da + db * db) * (1.0f / 64.0f);
        float rstd = rsqrtf(var + 1e-5f);
        g_tree[obase + q * 64 + lane]      = da * rstd * gma + bta + sa * ska;
        g_tree[obase + q * 64 + lane + 32] = db * rstd * gmb + btb + sa * skb;
    }
}

// ---------------- small-level merge (round-7 verified SIMT path) ----------------
template <int KC, int NPW>
__global__ void __launch_bounds__(256) merge_kernel(int d, int lo,
                             const float* __restrict__ glb, const float* __restrict__ grb,
                             const float* __restrict__ ln_g, const float* __restrict__ ln_b)
{
    constexpr int NS = 2 * KC;
    __shared__ float s_gin[8][NPW][2][160];
    int warp = threadIdx.x >> 5;
    int lane = threadIdx.x & 31;
    int inst = blockIdx.x * 8 + warp;
    int ngroups = lo / NPW;
    if (inst >= ngroups * 8) return;
    int node0 = lo + (inst >> 3) * NPW;
    int h = inst & 7;

    float pr = g_pr[d][h], pi = g_pi[d][h];
    float dvl = g_dv[d][lane];

    float fla[NPW][2][KC], flb[NPW][2][KC], rta[NPW][2][KC], rtb[NPW][2][KC];
#pragma unroll
    for (int j = 0; j < NPW; j++) {
        int node = node0 + j;
#pragma unroll
        for (int b = 0; b < 2; b++) {
            const float* tl = g_tree + (size_t)(((2 * node) * 2 + b) * 8 + h) * 128;
            const float* tr = g_tree + (size_t)(((2 * node + 1) * 2 + b) * 8 + h) * 128;
#pragma unroll
            for (int k = 0; k < KC; k++) {
                fla[j][b][k] = tl[k * 64 + lane];
                flb[j][b][k] = tl[k * 64 + lane + 32];
                float fr = tr[k * 64 + lane];
                float fi = tr[k * 64 + lane + 32];
                rta[j][b][k] = pr * fr - pi * fi;
                rtb[j][b][k] = pi * fr + pr * fi;
            }
            float lma, lmb, rma, rmb;
            if (KC == 2) {
                lma = 0.5f * (fla[j][b][0] + fla[j][b][1]); lmb = 0.5f * (flb[j][b][0] + flb[j][b][1]);
                rma = 0.5f * (rta[j][b][0] + rta[j][b][1]); rmb = 0.5f * (rtb[j][b][0] + rtb[j][b][1]);
            } else {
                lma = fla[j][b][0]; lmb = flb[j][b][0]; rma = rta[j][b][0]; rmb = rtb[j][b][0];
            }
            float* gin = s_gin[warp][j][b];
            gin[lane] = lma; gin[lane + 32] = lmb;
            gin[64 + lane] = rma; gin[96 + lane] = rmb;
            gin[128 + lane] = dvl;
        }
    }
    __syncwarp();

    float al0[NPW][2], al1[NPW][2], ar0[NPW][2], ar1[NPW][2];
    {
        float bl0 = glb[lane], bl1 = glb[lane + 32];
        float br0 = grb[lane], br1 = grb[lane + 32];
#pragma unroll
        for (int j = 0; j < NPW; j++)
#pragma unroll
            for (int b = 0; b < 2; b++) {
                al0[j][b] = bl0; al1[j][b] = bl1;
                ar0[j][b] = br0; ar1[j][b] = br1;
            }
    }
#pragma unroll 2
    for (int i = 0; i < 160; i++) {
        float4 w = g_gw[i][lane];
#pragma unroll
        for (int j = 0; j < NPW; j++)
#pragma unroll
            for (int b = 0; b < 2; b++) {
                float gi = s_gin[warp][j][b][i];
                al0[j][b] = fmaf(w.x, gi, al0[j][b]); al1[j][b] = fmaf(w.y, gi, al1[j][b]);
                ar0[j][b] = fmaf(w.z, gi, ar0[j][b]); ar1[j][b] = fmaf(w.w, gi, ar1[j][b]);
            }
    }

    float ska[NPW][2], skb[NPW][2];
#pragma unroll
    for (int j = 0; j < NPW; j++)
#pragma unroll
        for (int b = 0; b < 2; b++) { ska[j][b] = 0.0f; skb[j][b] = 0.0f; }
#pragma unroll 2
    for (int i = 0; i < 64; i++) {
        float2 w = g_skw[i][lane];
#pragma unroll
        for (int j = 0; j < NPW; j++)
#pragma unroll
            for (int b = 0; b < 2; b++) {
                float l = s_gin[warp][j][b][i];
                ska[j][b] = fmaf(w.x, l, ska[j][b]);
                skb[j][b] = fmaf(w.y, l, skb[j][b]);
            }
    }

    float sa = g_sigalpha;
    float gma = ln_g[lane], gmb = ln_g[lane + 32];
    float bta = ln_b[lane], btb = ln_b[lane + 32];

#pragma unroll
    for (int j = 0; j < NPW; j++) {
        int node = node0 + j;
#pragma unroll
        for (int b = 0; b < 2; b++) {
            float gla = sigf(al0[j][b]), glv = sigf(al1[j][b]);
            float gra = sigf(ar0[j][b]), grv = sigf(ar1[j][b]);

            float bka[NS], bkb[NS];
#pragma unroll
            for (int k = 0; k < KC; k++) {
                bka[k] = fla[j][b][k] * gla;      bkb[k] = flb[j][b][k] * glv;
                bka[KC + k] = rta[j][b][k] * gra; bkb[KC + k] = rtb[j][b][k] * grv;
            }
            size_t obase = (size_t)((node * 2 + b) * 8 + h) * 128;

#pragma unroll
            for (int q = 0; q < 2; q++) {
                float pqa = g_pq[d][q][lane], pqb = g_pq[d][q][lane + 32];
                float sc[NS];
#pragma unroll
                for (int s = 0; s < NS; s++) {
                    float p = pqa * bka[s] + pqb * bkb[s];
                    sc[s] = wsum(p) * 0.125f;
                }
                float mx = sc[0];
#pragma unroll
                for (int s = 1; s < NS; s++) mx = fmaxf(mx, sc[s]);
                float den = 0.0f;
#pragma unroll
                for (int s = 0; s < NS; s++) { sc[s] = __expf(sc[s] - mx); den += sc[s]; }
                float inv = 1.0f / den;
                float ra = 0.0f, rb = 0.0f;
#pragma unroll
                for (int s = 0; s < NS; s++) {
                    float w = sc[s] * inv;
                    ra = fmaf(w, bka[s], ra);
                    rb = fmaf(w, bkb[s], rb);
                }
                float mu = wsum(ra + rb) * (1.0f / 64.0f);
                float da = ra - mu, db = rb - mu;
                float var = wsum(da * da + db * db) * (1.0f / 64.0f);
                float rstd = rsqrtf(var + 1e-5f);
                g_tree[obase + q * 64 + lane]      = da * rstd * gma + bta + sa * ska[j][b];
                g_tree[obase + q * 64 + lane + 32] = db * rstd * gmb + btb + sa * skb[j][b];
            }
        }
    }
}

// ---------------- u = W_s^T v for the 2048 cover-reachable (node,depth) entries ----------------
__global__ void utransform_kernel(const float* __restrict__ dpw)
{
    __shared__ float sv[8][4][64];
    int e = blockIdx.x;                    // 0..2047
    int h = threadIdx.x >> 5, lane = threadIdx.x & 31;

    int s = 0, base = 0;
#pragma unroll
    for (int ss = 0; ss < 12; ss++) {
        int cnt = 1024 >> ss; if (cnt == 0) cnt = 1;
        if (e >= base + cnt) { base += cnt; s = ss + 1; }
        else break;
    }
    int node = (1 << (12 - s)) + 2 * (e - base);
    int kv = (s == 0) ? 1 : 2;
    int nvec = 2 * kv;
    const float* W = dpw + (size_t)s * 4096;

    for (int j = 0; j < nvec; j++) {
        int b = j / kv, k = j % kv;
        const float* src = g_tree + (size_t)((node * 2 + b) * 8 + h) * 128 + k * 64;
        sv[h][j][lane] = src[lane];
        sv[h][j][lane + 32] = src[lane + 32];
    }
    __syncwarp();

    float u0[4] = {0, 0, 0, 0}, u1[4] = {0, 0, 0, 0};
    for (int o = 0; o < 64; o++) {
        float w0 = W[o * 64 + lane];
        float w1 = W[o * 64 + lane + 32];
#pragma unroll
        for (int j = 0; j < 4; j++) {
            if (j < nvec) {
                float v = sv[h][j][o];
                u0[j] = fmaf(w0, v, u0[j]);
                u1[j] = fmaf(w1, v, u1[j]);
            }
        }
    }
    for (int j = 0; j < nvec; j++) {
        int b = j / kv, k = j % kv;
        float* dst = g_u + (size_t)((node * 2 + b) * 8 + h) * 128 + k * 64;
        dst[lane] = u0[j];
        dst[lane + 32] = u1[j];
    }
}

// ---------------- cover attention: one warp per (t,b,h), scores use q.(v+u) ----------------
__global__ void cover_attn_kernel()
{
    int t = blockIdx.x, b = blockIdx.y;
    int h = threadIdx.x >> 5, lane = threadIdx.x & 31;
    int pos = t + 1;
    const float* qp = g_qbase + (size_t)(b * LL + t) * DMODEL + h * 64;
    float qa = qp[lane], qb = qp[lane + 32];

    float m = -1e30f, den = 0.0f, ca = 0.0f, cb = 0.0f;
#pragma unroll
    for (int s = 0; s < 12; s++) {
        if ((pos >> s) & 1) {
            int node = ((LEAF + pos) >> s) - 1;
            float scl = g_scale[s];
            size_t off = (size_t)((node * 2 + b) * 8 + h) * 128;
            int kv = (s == 0) ? 1 : 2;
            for (int k = 0; k < kv; k++) {
                float va = g_tree[off + k * 64 + lane];
                float vb = g_tree[off + k * 64 + lane + 32];
                float ua = g_u[off + k * 64 + lane];
                float ub = g_u[off + k * 64 + lane + 32];
                float dot = wsum(qa * (va + ua) + qb * (vb + ub)) * scl;
                float nm = fmaxf(m, dot);
                float f = __expf(m - nm);
                float e = __expf(dot - nm);
                den = den * f + e;
                ca = ca * f + e * va;
                cb = cb * f + e * vb;
                m = nm;
            }
        }
    }
    float inv = 1.0f / den;
    size_t o = (size_t)(b * LL + t) * DMODEL + h * 64;
    g_ctx[o + lane] = ca * inv;
    g_ctx[o + lane + 32] = cb * inv;
}

// ---------------- launcher ----------------
extern "C" void kernel_launch(void* const* d_in, const int* in_sizes, int n_in,
                              void* d_out, int out_size)
{
    const float* x      = (const float*)d_in[0];
    const float* Wq     = (const float*)d_in[1];
    const float* Wv     = (const float*)d_in[2];
    const float* Wo     = (const float*)d_in[3];
    const float* glw    = (const float*)d_in[4];
    const float* glb    = (const float*)d_in[5];
    const float* grw    = (const float*)d_in[6];
    const float* grb    = (const float*)d_in[7];
    const float* pqb    = (const float*)d_in[8];
    const float* qow    = (const float*)d_in[9];
    const float* qob    = (const float*)d_in[10];
    const float* lng    = (const float*)d_in[11];
    const float* lnb    = (const float*)d_in[12];
    const float* skw    = (const float*)d_in[13];
    const float* salpha = (const float*)d_in[14];
    const float* wfreq  = (const float*)d_in[15];
    const float* wdamp  = (const float*)d_in[16];
    const float* wphase = (const float*)d_in[17];
    const float* dpw    = (const float*)d_in[18];
    const float* dtemp  = (const float*)d_in[19];

    precompute_kernel<<<1, 256>>>(glw, grw, pqb, qow, qob, skw, salpha,
                                  wfreq, wdamp, wphase, dtemp);

    // q_base = x @ Wq^T ; v -> tree leaves = x @ Wv^T   (bf16-split tensor cores)
    gemm_bf16s<2, 0><<<dim3(32, 4), 256>>>(x, Wq, nullptr);
    gemm_bf16s<1, 0><<<dim3(32, 4), 256>>>(x, Wv, nullptr);

    // tree merges, levels 1..11 (root unused by covers)
    for (int d = 1; d <= 11; d++) {
        int lo = 1 << (12 - d);
        if (lo >= 128) {                  // d = 1..5: prepare -> tensor GEMM -> epilogue
            int M = lo * 16;
            if (d == 1) merge_prep<1><<<lo * 2, 256>>>(d, lo);
            else        merge_prep<2><<<lo * 2, 256>>>(d, lo);
            gate_gemm<<<dim3(M / 128, 3), 256>>>(M);
            if (d == 1) merge_epi<1><<<lo * 2, 256>>>(d, lo, glb, grb, lng, lnb);
            else        merge_epi<2><<<lo * 2, 256>>>(d, lo, glb, grb, lng, lnb);
        } else if (lo >= 64) {
            merge_kernel<2, 2><<<lo / 2, 256>>>(d, lo, glb, grb, lng, lnb);
        } else {
            merge_kernel<2, 1><<<lo, 256>>>(d, lo, glb, grb, lng, lnb);
        }
    }

    // u = W_s^T v on cover-reachable nodes
    utransform_kernel<<<2048, 256>>>(dpw);

    // cover attention -> ctx
    cover_attn_kernel<<<dim3(LL, BB), 256>>>();

    // out = ctx @ Wo^T
    gemm_bf16s<0, 1><<<dim3(32, 4), 256>>>(nullptr, Wo, (float*)d_out);
}

// round 13
// speedup vs baseline: 1.1271x; 1.0530x over previous
#include <cuda_runtime.h>
#include <cuda_bf16.h>
#include <stdint.h>
#include <math.h>

// ---------------- problem constants ----------------
#define BB 2
#define LL 2048
#define HH 8
#define DMODEL 512
#define LEAF 4096

// ---------------- device scratch (static, no allocs) ----------------
__device__ float g_tree[8192 * 2 * 8 * 2 * 64];   // 64 MB  (node,b,h,k,d)
__device__ float g_u   [8192 * 2 * 8 * 2 * 64];   // 64 MB
__device__ float g_qbase[BB * LL * DMODEL];       // 8 MB
__device__ float g_ctx[BB * LL * DMODEL];         // 8 MB

__device__ float4 g_gw[160][32];
__device__ float2 g_skw[64][32];
__device__ float  g_dv[13][32];
__device__ float  g_pr[13][8];
__device__ float  g_pi[13][8];
__device__ float  g_pq[13][2][64];
__device__ float  g_scale[13];
__device__ float  g_sigalpha;

// ---------------- helpers ----------------
__device__ __forceinline__ float wsum(float v) {
    v += __shfl_xor_sync(0xffffffffu, v, 16);
    v += __shfl_xor_sync(0xffffffffu, v, 8);
    v += __shfl_xor_sync(0xffffffffu, v, 4);
    v += __shfl_xor_sync(0xffffffffu, v, 2);
    v += __shfl_xor_sync(0xffffffffu, v, 1);
    return v;
}
__device__ __forceinline__ float sigf(float x) { return 1.0f / (1.0f + __expf(-x)); }

__device__ __forceinline__ void split2(float x, float y, unsigned int& hp, unsigned int& lp) {
    __nv_bfloat162 hh, ll;
    hh.x = __float2bfloat16(x);
    hh.y = __float2bfloat16(y);
    ll.x = __float2bfloat16(x - __bfloat162float(hh.x));
    ll.y = __float2bfloat16(y - __bfloat162float(hh.y));
    hp = *reinterpret_cast<unsigned int*>(&hh);
    lp = *reinterpret_cast<unsigned int*>(&ll);
}

__device__ __forceinline__ void mma_bf16(float* c, const unsigned int* a, const unsigned int* b) {
    asm volatile(
        "mma.sync.aligned.m16n8k16.row.col.f32.bf16.bf16.f32 "
        "{%0,%1,%2,%3}, {%4,%5,%6,%7}, {%8,%9}, {%0,%1,%2,%3};"
        : "+f"(c[0]), "+f"(c[1]), "+f"(c[2]), "+f"(c[3])
        : "r"(a[0]), "r"(a[1]), "r"(a[2]), "r"(a[3]), "r"(b[0]), "r"(b[1]));
}

// ---------------- precompute small tables ----------------
__global__ void precompute_kernel(
    const float* __restrict__ glw, const float* __restrict__ grw,
    const float* __restrict__ pqb, const float* __restrict__ qow,
    const float* __restrict__ qob, const float* __restrict__ skw,
    const float* __restrict__ salpha, const float* __restrict__ wfreq,
    const float* __restrict__ wdamp, const float* __restrict__ wphase,
    const float* __restrict__ dtemp)
{
    int t = threadIdx.x;  // 256 threads

    for (int idx = t; idx < 160 * 32; idx += 256) {
        int i = idx >> 5, l = idx & 31;
        g_gw[i][l] = make_float4(glw[l * 160 + i], glw[(l + 32) * 160 + i],
                                 grw[l * 160 + i], grw[(l + 32) * 160 + i]);
    }
    for (int idx = t; idx < 64 * 32; idx += 256) {
        int i = idx >> 5, l = idx & 31;
        g_skw[i][l] = make_float2(skw[l * 64 + i], skw[(l + 32) * 64 + i]);
    }
    for (int idx = t; idx < 13 * 32; idx += 256) {
        int d = idx >> 5, e = idx & 31;
        int i = e >> 1;
        float inv = expf(-(2.0f * (float)i) * logf(10000.0f) / 32.0f);
        float a = (float)d * inv;
        g_dv[d][e] = (e & 1) ? cosf(a) : sinf(a);
    }
    if (t < 13 * 8) {
        int d = t >> 3, h = t & 7;
        float sp = log1pf(expf(wdamp[h]));
        float decay = expf(-sp);
        float ang = wfreq[h] + wphase[h] + (float)d * 0.78539816339744831f;
        g_pr[d][h] = decay * cosf(ang);
        g_pi[d][h] = decay * sinf(ang);
    }
    if (t < 13) {
        float sp = log1pf(expf(dtemp[t]));
        g_scale[t] = 1.0f / ((sp + 1e-6f) * 8.0f);
    }
    if (t == 0) g_sigalpha = 1.0f / (1.0f + expf(-salpha[0]));

    __syncthreads();

    for (int idx = t; idx < 13 * 128; idx += 256) {
        int d = idx >> 7, kj = idx & 127;
        float s = pqb[kj] + qob[kj];
        for (int e = 0; e < 32; e++) s += qow[kj * 32 + e] * g_dv[d][e];
        g_pq[d][kj >> 6][kj & 63] = s;
    }
}

// ---------------- bf16-split tensor-core GEMM: C = A(4096x512) @ W(512x512)^T ----------------
template <int MODE, int ASRC>
__global__ void __launch_bounds__(256) gemm_bf16s(const float* __restrict__ A,
                                                  const float* __restrict__ W,
                                                  float* __restrict__ C)
{
    __shared__ unsigned int Ah[128][12], Al[128][12], Bh[128][12], Bl[128][12];
    const float* Ab = (ASRC == 0) ? A : g_ctx;
    int t = threadIdx.x;
    int lane = t & 31, wid = t >> 5;
    int wm = (wid & 1) * 64, wn = (wid >> 1) * 32;
    int m0 = blockIdx.x * 128, n0 = blockIdx.y * 128;
    int g = lane >> 2, tq = lane & 3;

    float c[4][4][4];
#pragma unroll
    for (int i = 0; i < 4; i++)
#pragma unroll
        for (int j = 0; j < 4; j++)
#pragma unroll
            for (int k = 0; k < 4; k++) c[i][j][k] = 0.0f;

    for (int k0 = 0; k0 < DMODEL; k0 += 16) {
#pragma unroll
        for (int j = 0; j < 2; j++) {
            int q = t + 256 * j;
            int row = q >> 2, kq = q & 3;
            float4 va = *(const float4*)(Ab + (size_t)(m0 + row) * DMODEL + k0 + kq * 4);
            unsigned int hp, lp;
            split2(va.x, va.y, hp, lp); Ah[row][kq * 2] = hp;     Al[row][kq * 2] = lp;
            split2(va.z, va.w, hp, lp); Ah[row][kq * 2 + 1] = hp; Al[row][kq * 2 + 1] = lp;
            float4 vb = *(const float4*)(W + (size_t)(n0 + row) * DMODEL + k0 + kq * 4);
            split2(vb.x, vb.y, hp, lp); Bh[row][kq * 2] = hp;     Bl[row][kq * 2] = lp;
            split2(vb.z, vb.w, hp, lp); Bh[row][kq * 2 + 1] = hp; Bl[row][kq * 2 + 1] = lp;
        }
        __syncthreads();

        unsigned int ah[4][4], al[4][4], bh[4][2], bl[4][2];
#pragma unroll
        for (int mt = 0; mt < 4; mt++) {
            int r = wm + mt * 16 + g;
            ah[mt][0] = Ah[r][tq];     ah[mt][1] = Ah[r + 8][tq];
            ah[mt][2] = Ah[r][tq + 4]; ah[mt][3] = Ah[r + 8][tq + 4];
            al[mt][0] = Al[r][tq];     al[mt][1] = Al[r + 8][tq];
            al[mt][2] = Al[r][tq + 4]; al[mt][3] = Al[r + 8][tq + 4];
        }
#pragma unroll
        for (int nt = 0; nt < 4; nt++) {
            int n = wn + nt * 8 + g;
            bh[nt][0] = Bh[n][tq]; bh[nt][1] = Bh[n][tq + 4];
            bl[nt][0] = Bl[n][tq]; bl[nt][1] = Bl[n][tq + 4];
        }
#pragma unroll
        for (int mt = 0; mt < 4; mt++)
#pragma unroll
            for (int nt = 0; nt < 4; nt++) {
                mma_bf16(c[mt][nt], ah[mt], bh[nt]);
                mma_bf16(c[mt][nt], al[mt], bh[nt]);
                mma_bf16(c[mt][nt], ah[mt], bl[nt]);
            }
        __syncthreads();
    }

#pragma unroll
    for (int mt = 0; mt < 4; mt++)
#pragma unroll
        for (int nt = 0; nt < 4; nt++) {
            int r0 = m0 + wm + mt * 16 + g;
            int cc = n0 + wn + nt * 8 + tq * 2;
            float2 v0 = make_float2(c[mt][nt][0], c[mt][nt][1]);
            float2 v1 = make_float2(c[mt][nt][2], c[mt][nt][3]);
            if (MODE == 0) {
                *(float2*)(C + (size_t)r0 * DMODEL + cc) = v0;
                *(float2*)(C + (size_t)(r0 + 8) * DMODEL + cc) = v1;
            } else if (MODE == 2) {
                *(float2*)(g_qbase + (size_t)r0 * DMODEL + cc) = v0;
                *(float2*)(g_qbase + (size_t)(r0 + 8) * DMODEL + cc) = v1;
            } else {
                int hh = cc >> 6, dd = cc & 63;
                int b0 = r0 >> 11, l0 = r0 & 2047;
                *(float2*)(g_tree + ((size_t)(((LEAF + l0) * 2 + b0) * 8 + hh)) * 128 + dd) = v0;
                int r1 = r0 + 8;
                int b1 = r1 >> 11, l1 = r1 & 2047;
                *(float2*)(g_tree + ((size_t)(((LEAF + l1) * 2 + b1) * 8 + hh)) * 128 + dd) = v1;
            }
        }
}

// ---------------- big-level merge: 2 nodes/warp, phased (low-register) ----------------
// Phase A: build packed gate inputs s_gin[warp][dim][j*2+b] (no child regs retained)
// Phase B: gate+skip fused loop; one LDS.128 broadcast feeds 16 gate FMAs per g_gw fetch
// Phase C: reload children (L1/L2 hot), verified round-7 epilogue math
template <int KC>
__global__ void __launch_bounds__(256) merge_npw2(int d, int lo,
                             const float* __restrict__ glb, const float* __restrict__ grb,
                             const float* __restrict__ ln_g, const float* __restrict__ ln_b)
{
    constexpr int NS = 2 * KC;
    __shared__ float s_gin[8][160][4];
    int warp = threadIdx.x >> 5;
    int lane = threadIdx.x & 31;
    int grp = blockIdx.x * 8 + warp;       // (nodePair)*8 + h
    if (grp >= (lo >> 1) * 8) return;
    int node0 = lo + (grp >> 3) * 2;
    int h = grp & 7;

    float pr = g_pr[d][h], pi = g_pi[d][h];
    float dvl = g_dv[d][lane];

    // ---- Phase A ----
#pragma unroll
    for (int j = 0; j < 2; j++) {
        int node = node0 + j;
#pragma unroll
        for (int b = 0; b < 2; b++) {
            const float* tl = g_tree + (size_t)(((2 * node) * 2 + b) * 8 + h) * 128;
            const float* tr = g_tree + (size_t)(((2 * node + 1) * 2 + b) * 8 + h) * 128;
            float fla[KC], flb[KC], rta[KC], rtb[KC];
#pragma unroll
            for (int k = 0; k < KC; k++) {
                fla[k] = tl[k * 64 + lane];
                flb[k] = tl[k * 64 + lane + 32];
                float fr = tr[k * 64 + lane];
                float fi = tr[k * 64 + lane + 32];
                rta[k] = pr * fr - pi * fi;
                rtb[k] = pi * fr + pr * fi;
            }
            float lma, lmb, rma, rmb;
            if (KC == 2) {
                lma = 0.5f * (fla[0] + fla[1]); lmb = 0.5f * (flb[0] + flb[1]);
                rma = 0.5f * (rta[0] + rta[1]); rmb = 0.5f * (rtb[0] + rtb[1]);
            } else {
                lma = fla[0]; lmb = flb[0]; rma = rta[0]; rmb = rtb[0];
            }
            int slot = j * 2 + b;
            s_gin[warp][lane][slot] = lma;
            s_gin[warp][lane + 32][slot] = lmb;
            s_gin[warp][64 + lane][slot] = rma;
            s_gin[warp][96 + lane][slot] = rmb;
            s_gin[warp][128 + lane][slot] = dvl;
        }
    }
    __syncwarp();

    // ---- Phase B: fused gate (160) + skip (first 64) ----
    float al0[2][2], al1[2][2], ar0[2][2], ar1[2][2], ska[2][2], skb[2][2];
    {
        float bl0 = glb[lane], bl1 = glb[lane + 32];
        float br0 = grb[lane], br1 = grb[lane + 32];
#pragma unroll
        for (int j = 0; j < 2; j++)
#pragma unroll
            for (int b = 0; b < 2; b++) {
                al0[j][b] = bl0; al1[j][b] = bl1;
                ar0[j][b] = br0; ar1[j][b] = br1;
                ska[j][b] = 0.0f; skb[j][b] = 0.0f;
            }
    }
#pragma unroll 2
    for (int i = 0; i < 64; i++) {
        float4 w = g_gw[i][lane];
        float2 w2 = g_skw[i][lane];
        float4 gv = *(const float4*)&s_gin[warp][i][0];
        float gval[2][2] = {{gv.x, gv.y}, {gv.z, gv.w}};
#pragma unroll
        for (int j = 0; j < 2; j++)
#pragma unroll
            for (int b = 0; b < 2; b++) {
                float gi = gval[j][b];
                al0[j][b] = fmaf(w.x, gi, al0[j][b]); al1[j][b] = fmaf(w.y, gi, al1[j][b]);
                ar0[j][b] = fmaf(w.z, gi, ar0[j][b]); ar1[j][b] = fmaf(w.w, gi, ar1[j][b]);
                ska[j][b] = fmaf(w2.x, gi, ska[j][b]); skb[j][b] = fmaf(w2.y, gi, skb[j][b]);
            }
    }
#pragma unroll 2
    for (int i = 64; i < 160; i++) {
        float4 w = g_gw[i][lane];
        float4 gv = *(const float4*)&s_gin[warp][i][0];
        float gval[2][2] = {{gv.x, gv.y}, {gv.z, gv.w}};
#pragma unroll
        for (int j = 0; j < 2; j++)
#pragma unroll
            for (int b = 0; b < 2; b++) {
                float gi = gval[j][b];
                al0[j][b] = fmaf(w.x, gi, al0[j][b]); al1[j][b] = fmaf(w.y, gi, al1[j][b]);
                ar0[j][b] = fmaf(w.z, gi, ar0[j][b]); ar1[j][b] = fmaf(w.w, gi, ar1[j][b]);
            }
    }

    // ---- Phase C: reload children, epilogue (round-7 verified math) ----
    float sa = g_sigalpha;
    float gma = ln_g[lane], gmb = ln_g[lane + 32];
    float bta = ln_b[lane], btb = ln_b[lane + 32];

#pragma unroll
    for (int j = 0; j < 2; j++) {
        int node = node0 + j;
#pragma unroll
        for (int b = 0; b < 2; b++) {
            const float* tl = g_tree + (size_t)(((2 * node) * 2 + b) * 8 + h) * 128;
            const float* tr = g_tree + (size_t)(((2 * node + 1) * 2 + b) * 8 + h) * 128;
            float fla[KC], flb[KC], rta[KC], rtb[KC];
#pragma unroll
            for (int k = 0; k < KC; k++) {
                fla[k] = tl[k * 64 + lane];
                flb[k] = tl[k * 64 + lane + 32];
                float fr = tr[k * 64 + lane];
                float fi = tr[k * 64 + lane + 32];
                rta[k] = pr * fr - pi * fi;
                rtb[k] = pi * fr + pr * fi;
            }
            float gla = sigf(al0[j][b]), glv = sigf(al1[j][b]);
            float gra = sigf(ar0[j][b]), grv = sigf(ar1[j][b]);

            float bka[NS], bkb[NS];
#pragma unroll
            for (int k = 0; k < KC; k++) {
                bka[k] = fla[k] * gla;      bkb[k] = flb[k] * glv;
                bka[KC + k] = rta[k] * gra; bkb[KC + k] = rtb[k] * grv;
            }
            size_t obase = (size_t)((node * 2 + b) * 8 + h) * 128;

#pragma unroll
            for (int q = 0; q < 2; q++) {
                float pqa = g_pq[d][q][lane], pqb = g_pq[d][q][lane + 32];
                float sc[NS];
#pragma unroll
                for (int s = 0; s < NS; s++) {
                    float p = pqa * bka[s] + pqb * bkb[s];
                    sc[s] = wsum(p) * 0.125f;
                }
                float mx = sc[0];
#pragma unroll
                for (int s = 1; s < NS; s++) mx = fmaxf(mx, sc[s]);
                float den = 0.0f;
#pragma unroll
                for (int s = 0; s < NS; s++) { sc[s] = __expf(sc[s] - mx); den += sc[s]; }
                float inv = 1.0f / den;
                float ra = 0.0f, rb = 0.0f;
#pragma unroll
                for (int s = 0; s < NS; s++) {
                    float w = sc[s] * inv;
                    ra = fmaf(w, bka[s], ra);
                    rb = fmaf(w, bkb[s], rb);
                }
                float mu = wsum(ra + rb) * (1.0f / 64.0f);
                float da = ra - mu, db = rb - mu;
                float var = wsum(da * da + db * db) * (1.0f / 64.0f);
                float rstd = rsqrtf(var + 1e-5f);
                g_tree[obase + q * 64 + lane]      = da * rstd * gma + bta + sa * ska[j][b];
                g_tree[obase + q * 64 + lane + 32] = db * rstd * gmb + btb + sa * skb[j][b];
            }
        }
    }
}

// ---------------- small-level merge (round-7 verified, one warp per (node,h)) ----------------
template <int KC>
__global__ void merge_kernel(int d, int lo,
                             const float* __restrict__ glb, const float* __restrict__ grb,
                             const float* __restrict__ ln_g, const float* __restrict__ ln_b)
{
    constexpr int NS = 2 * KC;
    __shared__ float s_gin[8][2][160];
    int warp = threadIdx.x >> 5;
    int lane = threadIdx.x & 31;
    int inst = blockIdx.x * 8 + warp;
    if (inst >= lo * 8) return;
    int node = lo + (inst >> 3);
    int h = inst & 7;

    float pr = g_pr[d][h], pi = g_pi[d][h];
    float fla[2][KC], flb[2][KC], rta[2][KC], rtb[2][KC];
#pragma unroll
    for (int b = 0; b < 2; b++) {
        const float* tl = g_tree + (size_t)(((2 * node) * 2 + b) * 8 + h) * 128;
        const float* tr = g_tree + (size_t)(((2 * node + 1) * 2 + b) * 8 + h) * 128;
#pragma unroll
        for (int k = 0; k < KC; k++) {
            fla[b][k] = tl[k * 64 + lane];
            flb[b][k] = tl[k * 64 + lane + 32];
            float fr = tr[k * 64 + lane];
            float fi = tr[k * 64 + lane + 32];
            rta[b][k] = pr * fr - pi * fi;
            rtb[b][k] = pi * fr + pr * fi;
        }
        float lma, lmb, rma, rmb;
        if (KC == 2) {
            lma = 0.5f * (fla[b][0] + fla[b][1]); lmb = 0.5f * (flb[b][0] + flb[b][1]);
            rma = 0.5f * (rta[b][0] + rta[b][1]); rmb = 0.5f * (rtb[b][0] + rtb[b][1]);
        } else {
            lma = fla[b][0]; lmb = flb[b][0]; rma = rta[b][0]; rmb = rtb[b][0];
        }
        float* gin = s_gin[warp][b];
        gin[lane] = lma; gin[lane + 32] = lmb;
        gin[64 + lane] = rma; gin[96 + lane] = rmb;
        gin[128 + lane] = g_dv[d][lane];
    }
    __syncwarp();

    float al0[2], al1[2], ar0[2], ar1[2];
#pragma unroll
    for (int b = 0; b < 2; b++) {
        al0[b] = glb[lane]; al1[b] = glb[lane + 32];
        ar0[b] = grb[lane]; ar1[b] = grb[lane + 32];
    }
#pragma unroll 4
    for (int i = 0; i < 160; i++) {
        float4 w = g_gw[i][lane];
#pragma unroll
        for (int b = 0; b < 2; b++) {
            float gi = s_gin[warp][b][i];
            al0[b] = fmaf(w.x, gi, al0[b]); al1[b] = fmaf(w.y, gi, al1[b]);
            ar0[b] = fmaf(w.z, gi, ar0[b]); ar1[b] = fmaf(w.w, gi, ar1[b]);
        }
    }

    float ska[2], skb[2];
    ska[0] = ska[1] = skb[0] = skb[1] = 0.0f;
#pragma unroll 4
    for (int i = 0; i < 64; i++) {
        float2 w = g_skw[i][lane];
#pragma unroll
        for (int b = 0; b < 2; b++) {
            float l = s_gin[warp][b][i];
            ska[b] = fmaf(w.x, l, ska[b]);
            skb[b] = fmaf(w.y, l, skb[b]);
        }
    }

    float sa = g_sigalpha;
    float gma = ln_g[lane], gmb = ln_g[lane + 32];
    float bta = ln_b[lane], btb = ln_b[lane + 32];

#pragma unroll
    for (int b = 0; b < 2; b++) {
        float gla = sigf(al0[b]), glv = sigf(al1[b]);
        float gra = sigf(ar0[b]), grv = sigf(ar1[b]);

        float bka[NS], bkb[NS];
#pragma unroll
        for (int k = 0; k < KC; k++) {
            bka[k] = fla[b][k] * gla;      bkb[k] = flb[b][k] * glv;
            bka[KC + k] = rta[b][k] * gra; bkb[KC + k] = rtb[b][k] * grv;
        }
        size_t obase = (size_t)((node * 2 + b) * 8 + h) * 128;

#pragma unroll
        for (int q = 0; q < 2; q++) {
            float pqa = g_pq[d][q][lane], pqb = g_pq[d][q][lane + 32];
            float sc[NS];
#pragma unroll
            for (int s = 0; s < NS; s++) {
                float p = pqa * bka[s] + pqb * bkb[s];
                sc[s] = wsum(p) * 0.125f;
            }
            float mx = sc[0];
#pragma unroll
            for (int s = 1; s < NS; s++) mx = fmaxf(mx, sc[s]);
            float den = 0.0f;
#pragma unroll
            for (int s = 0; s < NS; s++) { sc[s] = __expf(sc[s] - mx); den += sc[s]; }
            float inv = 1.0f / den;
            float ra = 0.0f, rb = 0.0f;
#pragma unroll
            for (int s = 0; s < NS; s++) {
                float w = sc[s] * inv;
                ra = fmaf(w, bka[s], ra);
                rb = fmaf(w, bkb[s], rb);
            }
            float mu = wsum(ra + rb) * (1.0f / 64.0f);
            float da = ra - mu, db = rb - mu;
            float var = wsum(da * da + db * db) * (1.0f / 64.0f);
            float rstd = rsqrtf(var + 1e-5f);
            g_tree[obase + q * 64 + lane]      = da * rstd * gma + bta + sa * ska[b];
            g_tree[obase + q * 64 + lane + 32] = db * rstd * gmb + btb + sa * skb[b];
        }
    }
}

// ---------------- u = W_s^T v for the 2048 cover-reachable (node,depth) entries ----------------
__global__ void utransform_kernel(const float* __restrict__ dpw)
{
    __shared__ float sv[8][4][64];
    int e = blockIdx.x;                    // 0..2047
    int h = threadIdx.x >> 5, lane = threadIdx.x & 31;

    int s = 0, base = 0;
#pragma unroll
    for (int ss = 0; ss < 12; ss++) {
        int cnt = 1024 >> ss; if (cnt == 0) cnt = 1;
        if (e >= base + cnt) { base += cnt; s = ss + 1; }
        else break;
    }
    int node = (1 << (12 - s)) + 2 * (e - base);
    int kv = (s == 0) ? 1 : 2;
    int nvec = 2 * kv;
    const float* W = dpw + (size_t)s * 4096;

    for (int j = 0; j < nvec; j++) {
        int b = j / kv, k = j % kv;
        const float* src = g_tree + (size_t)((node * 2 + b) * 8 + h) * 128 + k * 64;
        sv[h][j][lane] = src[lane];
        sv[h][j][lane + 32] = src[lane + 32];
    }
    __syncwarp();

    float u0[4] = {0, 0, 0, 0}, u1[4] = {0, 0, 0, 0};
    for (int o = 0; o < 64; o++) {
        float w0 = W[o * 64 + lane];
        float w1 = W[o * 64 + lane + 32];
#pragma unroll
        for (int j = 0; j < 4; j++) {
            if (j < nvec) {
                float v = sv[h][j][o];
                u0[j] = fmaf(w0, v, u0[j]);
                u1[j] = fmaf(w1, v, u1[j]);
            }
        }
    }
    for (int j = 0; j < nvec; j++) {
        int b = j / kv, k = j % kv;
        float* dst = g_u + (size_t)((node * 2 + b) * 8 + h) * 128 + k * 64;
        dst[lane] = u0[j];
        dst[lane + 32] = u1[j];
    }
}

// ---------------- cover attention: one warp per (t,b,h), scores use q.(v+u) ----------------
__global__ void cover_attn_kernel()
{
    int t = blockIdx.x, b = blockIdx.y;
    int h = threadIdx.x >> 5, lane = threadIdx.x & 31;
    int pos = t + 1;
    const float* qp = g_qbase + (size_t)(b * LL + t) * DMODEL + h * 64;
    float qa = qp[lane], qb = qp[lane + 32];

    float m = -1e30f, den = 0.0f, ca = 0.0f, cb = 0.0f;
#pragma unroll
    for (int s = 0; s < 12; s++) {
        if ((pos >> s) & 1) {
            int node = ((LEAF + pos) >> s) - 1;
            float scl = g_scale[s];
            size_t off = (size_t)((node * 2 + b) * 8 + h) * 128;
            int kv = (s == 0) ? 1 : 2;
            for (int k = 0; k < kv; k++) {
                float va = g_tree[off + k * 64 + lane];
                float vb = g_tree[off + k * 64 + lane + 32];
                float ua = g_u[off + k * 64 + lane];
                float ub = g_u[off + k * 64 + lane + 32];
                float dot = wsum(qa * (va + ua) + qb * (vb + ub)) * scl;
                float nm = fmaxf(m, dot);
                float f = __expf(m - nm);
                float e = __expf(dot - nm);
                den = den * f + e;
                ca = ca * f + e * va;
                cb = cb * f + e * vb;
                m = nm;
            }
        }
    }
    float inv = 1.0f / den;
    size_t o = (size_t)(b * LL + t) * DMODEL + h * 64;
    g_ctx[o + lane] = ca * inv;
    g_ctx[o + lane + 32] = cb * inv;
}

// ---------------- launcher ----------------
extern "C" void kernel_launch(void* const* d_in, const int* in_sizes, int n_in,
                              void* d_out, int out_size)
{
    const float* x      = (const float*)d_in[0];
    const float* Wq     = (const float*)d_in[1];
    const float* Wv     = (const float*)d_in[2];
    const float* Wo     = (const float*)d_in[3];
    const float* glw    = (const float*)d_in[4];
    const float* glb    = (const float*)d_in[5];
    const float* grw    = (const float*)d_in[6];
    const float* grb    = (const float*)d_in[7];
    const float* pqb    = (const float*)d_in[8];
    const float* qow    = (const float*)d_in[9];
    const float* qob    = (const float*)d_in[10];
    const float* lng    = (const float*)d_in[11];
    const float* lnb    = (const float*)d_in[12];
    const float* skw    = (const float*)d_in[13];
    const float* salpha = (const float*)d_in[14];
    const float* wfreq  = (const float*)d_in[15];
    const float* wdamp  = (const float*)d_in[16];
    const float* wphase = (const float*)d_in[17];
    const float* dpw    = (const float*)d_in[18];
    const float* dtemp  = (const float*)d_in[19];

    precompute_kernel<<<1, 256>>>(glw, grw, pqb, qow, qob, skw, salpha,
                                  wfreq, wdamp, wphase, dtemp);

    // q_base = x @ Wq^T ; v -> tree leaves = x @ Wv^T   (bf16-split tensor cores)
    gemm_bf16s<2, 0><<<dim3(32, 4), 256>>>(x, Wq, nullptr);
    gemm_bf16s<1, 0><<<dim3(32, 4), 256>>>(x, Wv, nullptr);

    // tree merges, levels 1..11 (root unused by covers)
    for (int d = 1; d <= 11; d++) {
        int lo = 1 << (12 - d);
        if (d == 1) {
            merge_npw2<1><<<lo / 2, 256>>>(d, lo, glb, grb, lng, lnb);
        } else if (lo >= 256) {          // d = 2..4
            merge_npw2<2><<<lo / 2, 256>>>(d, lo, glb, grb, lng, lnb);
        } else {
            merge_kernel<2><<<lo, 256>>>(d, lo, glb, grb, lng, lnb);
        }
    }

    // u = W_s^T v on cover-reachable nodes
    utransform_kernel<<<2048, 256>>>(dpw);

    // cover attention -> ctx
    cover_attn_kernel<<<dim3(LL, BB), 256>>>();

    // out = ctx @ Wo^T
    gemm_bf16s<0, 1><<<dim3(32, 4), 256>>>(nullptr, Wo, (float*)d_out);
}

// round 16
// speedup vs baseline: 1.1780x; 1.0452x over previous
#include <cuda_runtime.h>
#include <cuda_bf16.h>
#include <stdint.h>
#include <math.h>

// ---------------- problem constants ----------------
#define BB 2
#define LL 2048
#define HH 8
#define DMODEL 512
#define LEAF 4096

// ---------------- device scratch (static, no allocs) ----------------
__device__ float g_tree[8192 * 2 * 8 * 2 * 64];   // 64 MB  (node,b,h,k,d)
__device__ float g_u   [8192 * 2 * 8 * 2 * 64];   // 64 MB
__device__ float g_qbase[BB * LL * DMODEL];       // 8 MB
__device__ float g_ctx[BB * LL * DMODEL];         // 8 MB

__device__ float4 g_gw[160][32];
__device__ float2 g_skw[64][32];
__device__ float  g_glbe[13][64];   // glb + GL[:,128:160] @ dv[d]  (dv folded out)
__device__ float  g_grbe[13][64];   // grb + GR[:,128:160] @ dv[d]
__device__ float  g_dv[13][32];
__device__ float  g_pr[13][8];
__device__ float  g_pi[13][8];
__device__ float  g_pq[13][2][64];
__device__ float  g_scale[13];
__device__ float  g_sigalpha;

// ---------------- helpers ----------------
__device__ __forceinline__ float wsum(float v) {
    v += __shfl_xor_sync(0xffffffffu, v, 16);
    v += __shfl_xor_sync(0xffffffffu, v, 8);
    v += __shfl_xor_sync(0xffffffffu, v, 4);
    v += __shfl_xor_sync(0xffffffffu, v, 2);
    v += __shfl_xor_sync(0xffffffffu, v, 1);
    return v;
}
__device__ __forceinline__ float sigf(float x) { return 1.0f / (1.0f + __expf(-x)); }

__device__ __forceinline__ void split2(float x, float y, unsigned int& hp, unsigned int& lp) {
    __nv_bfloat162 hh, ll;
    hh.x = __float2bfloat16(x);
    hh.y = __float2bfloat16(y);
    ll.x = __float2bfloat16(x - __bfloat162float(hh.x));
    ll.y = __float2bfloat16(y - __bfloat162float(hh.y));
    hp = *reinterpret_cast<unsigned int*>(&hh);
    lp = *reinterpret_cast<unsigned int*>(&ll);
}

__device__ __forceinline__ void mma_bf16(float* c, const unsigned int* a, const unsigned int* b) {
    asm volatile(
        "mma.sync.aligned.m16n8k16.row.col.f32.bf16.bf16.f32 "
        "{%0,%1,%2,%3}, {%4,%5,%6,%7}, {%8,%9}, {%0,%1,%2,%3};"
        : "+f"(c[0]), "+f"(c[1]), "+f"(c[2]), "+f"(c[3])
        : "r"(a[0]), "r"(a[1]), "r"(a[2]), "r"(a[3]), "r"(b[0]), "r"(b[1]));
}

// ---------------- precompute small tables ----------------
__global__ void precompute_kernel(
    const float* __restrict__ glw, const float* __restrict__ grw,
    const float* __restrict__ pqb, const float* __restrict__ qow,
    const float* __restrict__ qob, const float* __restrict__ skw,
    const float* __restrict__ salpha, const float* __restrict__ wfreq,
    const float* __restrict__ wdamp, const float* __restrict__ wphase,
    const float* __restrict__ dtemp)
{
    int t = threadIdx.x;  // 256 threads

    for (int idx = t; idx < 160 * 32; idx += 256) {
        int i = idx >> 5, l = idx & 31;
        g_gw[i][l] = make_float4(glw[l * 160 + i], glw[(l + 32) * 160 + i],
                                 grw[l * 160 + i], grw[(l + 32) * 160 + i]);
    }
    for (int idx = t; idx < 64 * 32; idx += 256) {
        int i = idx >> 5, l = idx & 31;
        g_skw[i][l] = make_float2(skw[l * 64 + i], skw[(l + 32) * 64 + i]);
    }
    for (int idx = t; idx < 13 * 32; idx += 256) {
        int d = idx >> 5, e = idx & 31;
        int i = e >> 1;
        float inv = expf(-(2.0f * (float)i) * logf(10000.0f) / 32.0f);
        float a = (float)d * inv;
        g_dv[d][e] = (e & 1) ? cosf(a) : sinf(a);
    }
    if (t < 13 * 8) {
        int d = t >> 3, h = t & 7;
        float sp = log1pf(expf(wdamp[h]));
        float decay = expf(-sp);
        float ang = wfreq[h] + wphase[h] + (float)d * 0.78539816339744831f;
        g_pr[d][h] = decay * cosf(ang);
        g_pi[d][h] = decay * sinf(ang);
    }
    if (t < 13) {
        float sp = log1pf(expf(dtemp[t]));
        g_scale[t] = 1.0f / ((sp + 1e-6f) * 8.0f);
    }
    if (t == 0) g_sigalpha = 1.0f / (1.0f + expf(-salpha[0]));

    __syncthreads();   // g_dv ready

    // fold depth embedding into per-depth gate bias terms (bias added later)
    for (int idx = t; idx < 13 * 64; idx += 256) {
        int d = idx >> 6, j = idx & 63;
        float sl = 0.0f, sr = 0.0f;
        for (int e = 0; e < 32; e++) {
            sl += glw[j * 160 + 128 + e] * g_dv[d][e];
            sr += grw[j * 160 + 128 + e] * g_dv[d][e];
        }
        g_glbe[d][j] = sl;
        g_grbe[d][j] = sr;
    }

    for (int idx = t; idx < 13 * 128; idx += 256) {
        int d = idx >> 7, kj = idx & 127;
        float s = pqb[kj] + qob[kj];
        for (int e = 0; e < 32; e++) s += qow[kj * 32 + e] * g_dv[d][e];
        g_pq[d][kj >> 6][kj & 63] = s;
    }
}

// ---------------- add gate biases into the folded terms ----------------
__global__ void bias_fold_kernel(const float* __restrict__ glb, const float* __restrict__ grb)
{
    int t = threadIdx.x;
    for (int idx = t; idx < 13 * 64; idx += 256) {
        int d = idx >> 6, j = idx & 63;
        g_glbe[d][j] = glb[j] + g_glbe[d][j];
        g_grbe[d][j] = grb[j] + g_grbe[d][j];
    }
}

// ---------------- bf16-split tensor-core GEMM: C = A(4096x512) @ W(512x512)^T ----------------
// 32-wide k-chunks (two mma sub-passes per load) -> half the __syncthreads of the 16-wide version.
// Accumulation order along k is unchanged -> bitwise-identical results.
template <int MODE, int ASRC>
__global__ void __launch_bounds__(256) gemm_bf16s(const float* __restrict__ A,
                                                  const float* __restrict__ W,
                                                  float* __restrict__ C)
{
    __shared__ unsigned int Ah[128][18], Al[128][18], Bh[128][18], Bl[128][18];
    const float* Ab = (ASRC == 0) ? A : g_ctx;
    int t = threadIdx.x;
    int lane = t & 31, wid = t >> 5;
    int wm = (wid & 1) * 64, wn = (wid >> 1) * 32;
    int m0 = blockIdx.x * 128, n0 = blockIdx.y * 128;
    int g = lane >> 2, tq = lane & 3;

    float c[4][4][4];
#pragma unroll
    for (int i = 0; i < 4; i++)
#pragma unroll
        for (int j = 0; j < 4; j++)
#pragma unroll
            for (int k = 0; k < 4; k++) c[i][j][k] = 0.0f;

    for (int k0 = 0; k0 < DMODEL; k0 += 32) {
#pragma unroll
        for (int j = 0; j < 4; j++) {
            int q = t + 256 * j;            // 0..1023
            int row = q >> 3, kq = q & 7;   // 8 float4 per row = 32 floats
            float4 va = *(const float4*)(Ab + (size_t)(m0 + row) * DMODEL + k0 + kq * 4);
            unsigned int hp, lp;
            split2(va.x, va.y, hp, lp); Ah[row][kq * 2] = hp;     Al[row][kq * 2] = lp;
            split2(va.z, va.w, hp, lp); Ah[row][kq * 2 + 1] = hp; Al[row][kq * 2 + 1] = lp;
            float4 vb = *(const float4*)(W + (size_t)(n0 + row) * DMODEL + k0 + kq * 4);
            split2(vb.x, vb.y, hp, lp); Bh[row][kq * 2] = hp;     Bl[row][kq * 2] = lp;
            split2(vb.z, vb.w, hp, lp); Bh[row][kq * 2 + 1] = hp; Bl[row][kq * 2 + 1] = lp;
        }
        __syncthreads();

#pragma unroll
        for (int s = 0; s < 2; s++) {
            int o = s * 8;
            unsigned int ah[4][4], al[4][4], bh[4][2], bl[4][2];
#pragma unroll
            for (int mt = 0; mt < 4; mt++) {
                int r = wm + mt * 16 + g;
                ah[mt][0] = Ah[r][o + tq];     ah[mt][1] = Ah[r + 8][o + tq];
                ah[mt][2] = Ah[r][o + tq + 4]; ah[mt][3] = Ah[r + 8][o + tq + 4];
                al[mt][0] = Al[r][o + tq];     al[mt][1] = Al[r + 8][o + tq];
                al[mt][2] = Al[r][o + tq + 4]; al[mt][3] = Al[r + 8][o + tq + 4];
            }
#pragma unroll
            for (int nt = 0; nt < 4; nt++) {
                int n = wn + nt * 8 + g;
                bh[nt][0] = Bh[n][o + tq]; bh[nt][1] = Bh[n][o + tq + 4];
                bl[nt][0] = Bl[n][o + tq]; bl[nt][1] = Bl[n][o + tq + 4];
            }
#pragma unroll
            for (int mt = 0; mt < 4; mt++)
#pragma unroll
                for (int nt = 0; nt < 4; nt++) {
                    mma_bf16(c[mt][nt], ah[mt], bh[nt]);
                    mma_bf16(c[mt][nt], al[mt], bh[nt]);
                    mma_bf16(c[mt][nt], ah[mt], bl[nt]);
                }
        }
        __syncthreads();
    }

#pragma unroll
    for (int mt = 0; mt < 4; mt++)
#pragma unroll
        for (int nt = 0; nt < 4; nt++) {
            int r0 = m0 + wm + mt * 16 + g;
            int cc = n0 + wn + nt * 8 + tq * 2;
            float2 v0 = make_float2(c[mt][nt][0], c[mt][nt][1]);
            float2 v1 = make_float2(c[mt][nt][2], c[mt][nt][3]);
            if (MODE == 0) {
                *(float2*)(C + (size_t)r0 * DMODEL + cc) = v0;
                *(float2*)(C + (size_t)(r0 + 8) * DMODEL + cc) = v1;
            } else if (MODE == 2) {
                *(float2*)(g_qbase + (size_t)r0 * DMODEL + cc) = v0;
                *(float2*)(g_qbase + (size_t)(r0 + 8) * DMODEL + cc) = v1;
            } else {
                int hh = cc >> 6, dd = cc & 63;
                int b0 = r0 >> 11, l0 = r0 & 2047;
                *(float2*)(g_tree + ((size_t)(((LEAF + l0) * 2 + b0) * 8 + hh)) * 128 + dd) = v0;
                int r1 = r0 + 8;
                int b1 = r1 >> 11, l1 = r1 & 2047;
                *(float2*)(g_tree + ((size_t)(((LEAF + l1) * 2 + b1) * 8 + hh)) * 128 + dd) = v1;
            }
        }
}

// ---------------- big-level merge: 2 nodes/warp, phased, dv folded (128-dim gate loop) ----------------
template <int KC>
__global__ void __launch_bounds__(256) merge_npw2(int d, int lo,
                             const float* __restrict__ ln_g, const float* __restrict__ ln_b)
{
    constexpr int NS = 2 * KC;
    __shared__ float s_gin[8][128][4];
    int warp = threadIdx.x >> 5;
    int lane = threadIdx.x & 31;
    int grp = blockIdx.x * 8 + warp;
    if (grp >= (lo >> 1) * 8) return;
    int node0 = lo + (grp >> 3) * 2;
    int h = grp & 7;

    float pr = g_pr[d][h], pi = g_pi[d][h];

    // ---- Phase A ----
#pragma unroll
    for (int j = 0; j < 2; j++) {
        int node = node0 + j;
#pragma unroll
        for (int b = 0; b < 2; b++) {
            const float* tl = g_tree + (size_t)(((2 * node) * 2 + b) * 8 + h) * 128;
            const float* tr = g_tree + (size_t)(((2 * node + 1) * 2 + b) * 8 + h) * 128;
            float fla[KC], flb[KC], rta[KC], rtb[KC];
#pragma unroll
            for (int k = 0; k < KC; k++) {
                fla[k] = tl[k * 64 + lane];
                flb[k] = tl[k * 64 + lane + 32];
                float fr = tr[k * 64 + lane];
                float fi = tr[k * 64 + lane + 32];
                rta[k] = pr * fr - pi * fi;
                rtb[k] = pi * fr + pr * fi;
            }
            float lma, lmb, rma, rmb;
            if (KC == 2) {
                lma = 0.5f * (fla[0] + fla[1]); lmb = 0.5f * (flb[0] + flb[1]);
                rma = 0.5f * (rta[0] + rta[1]); rmb = 0.5f * (rtb[0] + rtb[1]);
            } else {
                lma = fla[0]; lmb = flb[0]; rma = rta[0]; rmb = rtb[0];
            }
            int slot = j * 2 + b;
            s_gin[warp][lane][slot] = lma;
            s_gin[warp][lane + 32][slot] = lmb;
            s_gin[warp][64 + lane][slot] = rma;
            s_gin[warp][96 + lane][slot] = rmb;
        }
    }
    __syncwarp();

    // ---- Phase B: fused gate (128, dv folded into bias) + skip (first 64) ----
    float al0[2][2], al1[2][2], ar0[2][2], ar1[2][2], ska[2][2], skb[2][2];
    {
        float bl0 = g_glbe[d][lane], bl1 = g_glbe[d][lane + 32];
        float br0 = g_grbe[d][lane], br1 = g_grbe[d][lane + 32];
#pragma unroll
        for (int j = 0; j < 2; j++)
#pragma unroll
            for (int b = 0; b < 2; b++) {
                al0[j][b] = bl0; al1[j][b] = bl1;
                ar0[j][b] = br0; ar1[j][b] = br1;
                ska[j][b] = 0.0f; skb[j][b] = 0.0f;
            }
    }
#pragma unroll 2
    for (int i = 0; i < 64; i++) {
        float4 w = g_gw[i][lane];
        float2 w2 = g_skw[i][lane];
        float4 gv = *(const float4*)&s_gin[warp][i][0];
        float gval[2][2] = {{gv.x, gv.y}, {gv.z, gv.w}};
#pragma unroll
        for (int j = 0; j < 2; j++)
#pragma unroll
            for (int b = 0; b < 2; b++) {
                float gi = gval[j][b];
                al0[j][b] = fmaf(w.x, gi, al0[j][b]); al1[j][b] = fmaf(w.y, gi, al1[j][b]);
                ar0[j][b] = fmaf(w.z, gi, ar0[j][b]); ar1[j][b] = fmaf(w.w, gi, ar1[j][b]);
                ska[j][b] = fmaf(w2.x, gi, ska[j][b]); skb[j][b] = fmaf(w2.y, gi, skb[j][b]);
            }
    }
#pragma unroll 2
    for (int i = 64; i < 128; i++) {
        float4 w = g_gw[i][lane];
        float4 gv = *(const float4*)&s_gin[warp][i][0];
        float gval[2][2] = {{gv.x, gv.y}, {gv.z, gv.w}};
#pragma unroll
        for (int j = 0; j < 2; j++)
#pragma unroll
            for (int b = 0; b < 2; b++) {
                float gi = gval[j][b];
                al0[j][b] = fmaf(w.x, gi, al0[j][b]); al1[j][b] = fmaf(w.y, gi, al1[j][b]);
                ar0[j][b] = fmaf(w.z, gi, ar0[j][b]); ar1[j][b] = fmaf(w.w, gi, ar1[j][b]);
            }
    }

    // ---- Phase C: reload children, epilogue (verified math) ----
    float sa = g_sigalpha;
    float gma = ln_g[lane], gmb = ln_g[lane + 32];
    float bta = ln_b[lane], btb = ln_b[lane + 32];

#pragma unroll
    for (int j = 0; j < 2; j++) {
        int node = node0 + j;
#pragma unroll
        for (int b = 0; b < 2; b++) {
            const float* tl = g_tree + (size_t)(((2 * node) * 2 + b) * 8 + h) * 128;
            const float* tr = g_tree + (size_t)(((2 * node + 1) * 2 + b) * 8 + h) * 128;
            float fla[KC], flb[KC], rta[KC], rtb[KC];
#pragma unroll
            for (int k = 0; k < KC; k++) {
                fla[k] = tl[k * 64 + lane];
                flb[k] = tl[k * 64 + lane + 32];
                float fr = tr[k * 64 + lane];
                float fi = tr[k * 64 + lane + 32];
                rta[k] = pr * fr - pi * fi;
                rtb[k] = pi * fr + pr * fi;
            }
            float gla = sigf(al0[j][b]), glv = sigf(al1[j][b]);
            float gra = sigf(ar0[j][b]), grv = sigf(ar1[j][b]);

            float bka[NS], bkb[NS];
#pragma unroll
            for (int k = 0; k < KC; k++) {
                bka[k] = fla[k] * gla;      bkb[k] = flb[k] * glv;
                bka[KC + k] = rta[k] * gra; bkb[KC + k] = rtb[k] * grv;
            }
            size_t obase = (size_t)((node * 2 + b) * 8 + h) * 128;

#pragma unroll
            for (int q = 0; q < 2; q++) {
                float pqa = g_pq[d][q][lane], pqb = g_pq[d][q][lane + 32];
                float sc[NS];
#pragma unroll
                for (int s = 0; s < NS; s++) {
                    float p = pqa * bka[s] + pqb * bkb[s];
                    sc[s] = wsum(p) * 0.125f;
                }
                float mx = sc[0];
#pragma unroll
                for (int s = 1; s < NS; s++) mx = fmaxf(mx, sc[s]);
                float den = 0.0f;
#pragma unroll
                for (int s = 0; s < NS; s++) { sc[s] = __expf(sc[s] - mx); den += sc[s]; }
                float inv = 1.0f / den;
                float ra = 0.0f, rb = 0.0f;
#pragma unroll
                for (int s = 0; s < NS; s++) {
                    float w = sc[s] * inv;
                    ra = fmaf(w, bka[s], ra);
                    rb = fmaf(w, bkb[s], rb);
                }
                float mu = wsum(ra + rb) * (1.0f / 64.0f);
                float da = ra - mu, db = rb - mu;
                float var = wsum(da * da + db * db) * (1.0f / 64.0f);
                float rstd = rsqrtf(var + 1e-5f);
                g_tree[obase + q * 64 + lane]      = da * rstd * gma + bta + sa * ska[j][b];
                g_tree[obase + q * 64 + lane + 32] = db * rstd * gmb + btb + sa * skb[j][b];
            }
        }
    }
}

// ---------------- small-level merge (dv folded, 128-dim gate loop) ----------------
template <int KC>
__global__ void merge_kernel(int d, int lo,
                             const float* __restrict__ ln_g, const float* __restrict__ ln_b)
{
    constexpr int NS = 2 * KC;
    __shared__ float s_gin[8][2][128];
    int warp = threadIdx.x >> 5;
    int lane = threadIdx.x & 31;
    int inst = blockIdx.x * 8 + warp;
    if (inst >= lo * 8) return;
    int node = lo + (inst >> 3);
    int h = inst & 7;

    float pr = g_pr[d][h], pi = g_pi[d][h];
    float fla[2][KC], flb[2][KC], rta[2][KC], rtb[2][KC];
#pragma unroll
    for (int b = 0; b < 2; b++) {
        const float* tl = g_tree + (size_t)(((2 * node) * 2 + b) * 8 + h) * 128;
        const float* tr = g_tree + (size_t)(((2 * node + 1) * 2 + b) * 8 + h) * 128;
#pragma unroll
        for (int k = 0; k < KC; k++) {
            fla[b][k] = tl[k * 64 + lane];
            flb[b][k] = tl[k * 64 + lane + 32];
            float fr = tr[k * 64 + lane];
            float fi = tr[k * 64 + lane + 32];
            rta[b][k] = pr * fr - pi * fi;
            rtb[b][k] = pi * fr + pr * fi;
        }
        float lma, lmb, rma, rmb;
        if (KC == 2) {
            lma = 0.5f * (fla[b][0] + fla[b][1]); lmb = 0.5f * (flb[b][0] + flb[b][1]);
            rma = 0.5f * (rta[b][0] + rta[b][1]); rmb = 0.5f * (rtb[b][0] + rtb[b][1]);
        } else {
            lma = fla[b][0]; lmb = flb[b][0]; rma = rta[b][0]; rmb = rtb[b][0];
        }
        float* gin = s_gin[warp][b];
        gin[lane] = lma; gin[lane + 32] = lmb;
        gin[64 + lane] = rma; gin[96 + lane] = rmb;
    }
    __syncwarp();

    float al0[2], al1[2], ar0[2], ar1[2];
#pragma unroll
    for (int b = 0; b < 2; b++) {
        al0[b] = g_glbe[d][lane]; al1[b] = g_glbe[d][lane + 32];
        ar0[b] = g_grbe[d][lane]; ar1[b] = g_grbe[d][lane + 32];
    }
#pragma unroll 4
    for (int i = 0; i < 128; i++) {
        float4 w = g_gw[i][lane];
#pragma unroll
        for (int b = 0; b < 2; b++) {
            float gi = s_gin[warp][b][i];
            al0[b] = fmaf(w.x, gi, al0[b]); al1[b] = fmaf(w.y, gi, al1[b]);
            ar0[b] = fmaf(w.z, gi, ar0[b]); ar1[b] = fmaf(w.w, gi, ar1[b]);
        }
    }

    float ska[2], skb[2];
    ska[0] = ska[1] = skb[0] = skb[1] = 0.0f;
#pragma unroll 4
    for (int i = 0; i < 64; i++) {
        float2 w = g_skw[i][lane];
#pragma unroll
        for (int b = 0; b < 2; b++) {
            float l = s_gin[warp][b][i];
            ska[b] = fmaf(w.x, l, ska[b]);
            skb[b] = fmaf(w.y, l, skb[b]);
        }
    }

    float sa = g_sigalpha;
    float gma = ln_g[lane], gmb = ln_g[lane + 32];
    float bta = ln_b[lane], btb = ln_b[lane + 32];

#pragma unroll
    for (int b = 0; b < 2; b++) {
        float gla = sigf(al0[b]), glv = sigf(al1[b]);
        float gra = sigf(ar0[b]), grv = sigf(ar1[b]);

        float bka[NS], bkb[NS];
#pragma unroll
        for (int k = 0; k < KC; k++) {
            bka[k] = fla[b][k] * gla;      bkb[k] = flb[b][k] * glv;
            bka[KC + k] = rta[b][k] * gra; bkb[KC + k] = rtb[b][k] * grv;
        }
        size_t obase = (size_t)((node * 2 + b) * 8 + h) * 128;

#pragma unroll
        for (int q = 0; q < 2; q++) {
            float pqa = g_pq[d][q][lane], pqb = g_pq[d][q][lane + 32];
            float sc[NS];
#pragma unroll
            for (int s = 0; s < NS; s++) {
                float p = pqa * bka[s] + pqb * bkb[s];
                sc[s] = wsum(p) * 0.125f;
            }
            float mx = sc[0];
#pragma unroll
            for (int s = 1; s < NS; s++) mx = fmaxf(mx, sc[s]);
            float den = 0.0f;
#pragma unroll
            for (int s = 0; s < NS; s++) { sc[s] = __expf(sc[s] - mx); den += sc[s]; }
            float inv = 1.0f / den;
            float ra = 0.0f, rb = 0.0f;
#pragma unroll
            for (int s = 0; s < NS; s++) {
                float w = sc[s] * inv;
                ra = fmaf(w, bka[s], ra);
                rb = fmaf(w, bkb[s], rb);
            }
            float mu = wsum(ra + rb) * (1.0f / 64.0f);
            float da = ra - mu, db = rb - mu;
            float var = wsum(da * da + db * db) * (1.0f / 64.0f);
            float rstd = rsqrtf(var + 1e-5f);
            g_tree[obase + q * 64 + lane]      = da * rstd * gma + bta + sa * ska[b];
            g_tree[obase + q * 64 + lane + 32] = db * rstd * gmb + btb + sa * skb[b];
        }
    }
}

// ---------------- u = W_s^T v for the 2048 cover-reachable (node,depth) entries ----------------
__global__ void utransform_kernel(const float* __restrict__ dpw)
{
    __shared__ float sv[8][4][64];
    int e = blockIdx.x;                    // 0..2047
    int h = threadIdx.x >> 5, lane = threadIdx.x & 31;

    int s = 0, base = 0;
#pragma unroll
    for (int ss = 0; ss < 12; ss++) {
        int cnt = 1024 >> ss; if (cnt == 0) cnt = 1;
        if (e >= base + cnt) { base += cnt; s = ss + 1; }
        else break;
    }
    int node = (1 << (12 - s)) + 2 * (e - base);
    int kv = (s == 0) ? 1 : 2;
    int nvec = 2 * kv;
    const float* W = dpw + (size_t)s * 4096;

    for (int j = 0; j < nvec; j++) {
        int b = j / kv, k = j % kv;
        const float* src = g_tree + (size_t)((node * 2 + b) * 8 + h) * 128 + k * 64;
        sv[h][j][lane] = src[lane];
        sv[h][j][lane + 32] = src[lane + 32];
    }
    __syncwarp();

    float u0[4] = {0, 0, 0, 0}, u1[4] = {0, 0, 0, 0};
    for (int o = 0; o < 64; o++) {
        float w0 = W[o * 64 + lane];
        float w1 = W[o * 64 + lane + 32];
#pragma unroll
        for (int j = 0; j < 4; j++) {
            if (j < nvec) {
                float v = sv[h][j][o];
                u0[j] = fmaf(w0, v, u0[j]);
                u1[j] = fmaf(w1, v, u1[j]);
            }
        }
    }
    for (int j = 0; j < nvec; j++) {
        int b = j / kv, k = j % kv;
        float* dst = g_u + (size_t)((node * 2 + b) * 8 + h) * 128 + k * 64;
        dst[lane] = u0[j];
        dst[lane + 32] = u1[j];
    }
}

// ---------------- cover attention: one warp per (t,b,h), scores use q.(v+u) ----------------
__global__ void cover_attn_kernel()
{
    int t = blockIdx.x, b = blockIdx.y;
    int h = threadIdx.x >> 5, lane = threadIdx.x & 31;
    int pos = t + 1;
    const float* qp = g_qbase + (size_t)(b * LL + t) * DMODEL + h * 64;
    float qa = qp[lane], qb = qp[lane + 32];

    float m = -1e30f, den = 0.0f, ca = 0.0f, cb = 0.0f;
#pragma unroll
    for (int s = 0; s < 12; s++) {
        if ((pos >> s) & 1) {
            int node = ((LEAF + pos) >> s) - 1;
            float scl = g_scale[s];
            size_t off = (size_t)((node * 2 + b) * 8 + h) * 128;
            int kv = (s == 0) ? 1 : 2;
            for (int k = 0; k < kv; k++) {
                float va = g_tree[off + k * 64 + lane];
                float vb = g_tree[off + k * 64 + lane + 32];
                float ua = g_u[off + k * 64 + lane];
                float ub = g_u[off + k * 64 + lane + 32];
                float dot = wsum(qa * (va + ua) + qb * (vb + ub)) * scl;
                float nm = fmaxf(m, dot);
                float f = __expf(m - nm);
                float e = __expf(dot - nm);
                den = den * f + e;
                ca = ca * f + e * va;
                cb = cb * f + e * vb;
                m = nm;
            }
        }
    }
    float inv = 1.0f / den;
    size_t o = (size_t)(b * LL + t) * DMODEL + h * 64;
    g_ctx[o + lane] = ca * inv;
    g_ctx[o + lane + 32] = cb * inv;
}

// ---------------- launcher ----------------
extern "C" void kernel_launch(void* const* d_in, const int* in_sizes, int n_in,
                              void* d_out, int out_size)
{
    const float* x      = (const float*)d_in[0];
    const float* Wq     = (const float*)d_in[1];
    const float* Wv     = (const float*)d_in[2];
    const float* Wo     = (const float*)d_in[3];
    const float* glw    = (const float*)d_in[4];
    const float* glb    = (const float*)d_in[5];
    const float* grw    = (const float*)d_in[6];
    const float* grb    = (const float*)d_in[7];
    const float* pqb    = (const float*)d_in[8];
    const float* qow    = (const float*)d_in[9];
    const float* qob    = (const float*)d_in[10];
    const float* lng    = (const float*)d_in[11];
    const float* lnb    = (const float*)d_in[12];
    const float* skw    = (const float*)d_in[13];
    const float* salpha = (const float*)d_in[14];
    const float* wfreq  = (const float*)d_in[15];
    const float* wdamp  = (const float*)d_in[16];
    const float* wphase = (const float*)d_in[17];
    const float* dpw    = (const float*)d_in[18];
    const float* dtemp  = (const float*)d_in[19];

    precompute_kernel<<<1, 256>>>(glw, grw, pqb, qow, qob, skw, salpha,
                                  wfreq, wdamp, wphase, dtemp);
    bias_fold_kernel<<<1, 256>>>(glb, grb);

    // q_base = x @ Wq^T ; v -> tree leaves = x @ Wv^T   (bf16-split tensor cores)
    gemm_bf16s<2, 0><<<dim3(32, 4), 256>>>(x, Wq, nullptr);
    gemm_bf16s<1, 0><<<dim3(32, 4), 256>>>(x, Wv, nullptr);

    // tree merges, levels 1..11 (root unused by covers)
    for (int d = 1; d <= 11; d++) {
        int lo = 1 << (12 - d);
        if (d == 1) {
            merge_npw2<1><<<lo / 2, 256>>>(d, lo, lng, lnb);
        } else if (lo >= 256) {          // d = 2..4
            merge_npw2<2><<<lo / 2, 256>>>(d, lo, lng, lnb);
        } else {
            merge_kernel<2><<<lo, 256>>>(d, lo, lng, lnb);
        }
    }

    // u = W_s^T v on cover-reachable nodes
    utransform_kernel<<<2048, 256>>>(dpw);

    // cover attention -> ctx
    cover_attn_kernel<<<dim3(LL, BB), 256>>>();

    // out = ctx @ Wo^T
    gemm_bf16s<0, 1><<<dim3(32, 4), 256>>>(nullptr, Wo, (float*)d_out);
}

// round 17
// speedup vs baseline: 1.2047x; 1.0226x over previous
#include <cuda_runtime.h>
#include <cuda_bf16.h>
#include <stdint.h>
#include <math.h>

// ---------------- problem constants ----------------
#define BB 2
#define LL 2048
#define HH 8
#define DMODEL 512
#define LEAF 4096

// ---------------- device scratch (static, no allocs) ----------------
__device__ float g_tree[8192 * 2 * 8 * 2 * 64];   // 64 MB  (node,b,h,k,d)
__device__ float g_u   [8192 * 2 * 8 * 2 * 64];   // 64 MB
__device__ float g_qbase[BB * LL * DMODEL];       // 8 MB
__device__ float g_ctx[BB * LL * DMODEL];         // 8 MB

// pre-split bf16 hi/lo pair buffers (uint packs 2 consecutive-k bf16)
__device__ unsigned int g_Ah[4096 * 256];         // 4 MB
__device__ unsigned int g_Al[4096 * 256];         // 4 MB
__device__ unsigned int g_Wh[512 * 256];          // 0.5 MB
__device__ unsigned int g_Wl[512 * 256];          // 0.5 MB

__device__ float4 g_gw[160][32];
__device__ float2 g_skw[64][32];
__device__ float  g_glbe[13][64];
__device__ float  g_grbe[13][64];
__device__ float  g_dv[13][32];
__device__ float  g_pr[13][8];
__device__ float  g_pi[13][8];
__device__ float  g_pq[13][2][64];
__device__ float  g_scale[13];
__device__ float  g_sigalpha;

// ---------------- helpers ----------------
__device__ __forceinline__ float wsum(float v) {
    v += __shfl_xor_sync(0xffffffffu, v, 16);
    v += __shfl_xor_sync(0xffffffffu, v, 8);
    v += __shfl_xor_sync(0xffffffffu, v, 4);
    v += __shfl_xor_sync(0xffffffffu, v, 2);
    v += __shfl_xor_sync(0xffffffffu, v, 1);
    return v;
}
__device__ __forceinline__ float sigf(float x) { return 1.0f / (1.0f + __expf(-x)); }

__device__ __forceinline__ void split2(float x, float y, unsigned int& hp, unsigned int& lp) {
    __nv_bfloat162 hh, ll;
    hh.x = __float2bfloat16(x);
    hh.y = __float2bfloat16(y);
    ll.x = __float2bfloat16(x - __bfloat162float(hh.x));
    ll.y = __float2bfloat16(y - __bfloat162float(hh.y));
    hp = *reinterpret_cast<unsigned int*>(&hh);
    lp = *reinterpret_cast<unsigned int*>(&ll);
}

__device__ __forceinline__ void mma_bf16(float* c, const unsigned int* a, const unsigned int* b) {
    asm volatile(
        "mma.sync.aligned.m16n8k16.row.col.f32.bf16.bf16.f32 "
        "{%0,%1,%2,%3}, {%4,%5,%6,%7}, {%8,%9}, {%0,%1,%2,%3};"
        : "+f"(c[0]), "+f"(c[1]), "+f"(c[2]), "+f"(c[3])
        : "r"(a[0]), "r"(a[1]), "r"(a[2]), "r"(a[3]), "r"(b[0]), "r"(b[1]));
}

// ---------------- pre-split: fp32 -> packed bf16 hi/lo pair arrays ----------------
__global__ void presplit_kernel(const float* __restrict__ src,
                                unsigned int* __restrict__ dh,
                                unsigned int* __restrict__ dl, int npairs)
{
    int i = blockIdx.x * 256 + threadIdx.x;
    if (i < npairs) {
        float2 v = ((const float2*)src)[i];
        unsigned int hp, lp;
        split2(v.x, v.y, hp, lp);
        dh[i] = hp;
        dl[i] = lp;
    }
}
// variant reading from g_ctx (device global)
__global__ void presplit_ctx_kernel()
{
    int i = blockIdx.x * 256 + threadIdx.x;
    float2 v = ((const float2*)g_ctx)[i];
    unsigned int hp, lp;
    split2(v.x, v.y, hp, lp);
    g_Ah[i] = hp;
    g_Al[i] = lp;
}

// ---------------- precompute small tables ----------------
__global__ void precompute_kernel(
    const float* __restrict__ glw, const float* __restrict__ grw,
    const float* __restrict__ pqb, const float* __restrict__ qow,
    const float* __restrict__ qob, const float* __restrict__ skw,
    const float* __restrict__ salpha, const float* __restrict__ wfreq,
    const float* __restrict__ wdamp, const float* __restrict__ wphase,
    const float* __restrict__ dtemp)
{
    int t = threadIdx.x;  // 256 threads

    for (int idx = t; idx < 160 * 32; idx += 256) {
        int i = idx >> 5, l = idx & 31;
        g_gw[i][l] = make_float4(glw[l * 160 + i], glw[(l + 32) * 160 + i],
                                 grw[l * 160 + i], grw[(l + 32) * 160 + i]);
    }
    for (int idx = t; idx < 64 * 32; idx += 256) {
        int i = idx >> 5, l = idx & 31;
        g_skw[i][l] = make_float2(skw[l * 64 + i], skw[(l + 32) * 64 + i]);
    }
    for (int idx = t; idx < 13 * 32; idx += 256) {
        int d = idx >> 5, e = idx & 31;
        int i = e >> 1;
        float inv = expf(-(2.0f * (float)i) * logf(10000.0f) / 32.0f);
        float a = (float)d * inv;
        g_dv[d][e] = (e & 1) ? cosf(a) : sinf(a);
    }
    if (t < 13 * 8) {
        int d = t >> 3, h = t & 7;
        float sp = log1pf(expf(wdamp[h]));
        float decay = expf(-sp);
        float ang = wfreq[h] + wphase[h] + (float)d * 0.78539816339744831f;
        g_pr[d][h] = decay * cosf(ang);
        g_pi[d][h] = decay * sinf(ang);
    }
    if (t < 13) {
        float sp = log1pf(expf(dtemp[t]));
        g_scale[t] = 1.0f / ((sp + 1e-6f) * 8.0f);
    }
    if (t == 0) g_sigalpha = 1.0f / (1.0f + expf(-salpha[0]));

    __syncthreads();   // g_dv ready

    for (int idx = t; idx < 13 * 64; idx += 256) {
        int d = idx >> 6, j = idx & 63;
        float sl = 0.0f, sr = 0.0f;
        for (int e = 0; e < 32; e++) {
            sl += glw[j * 160 + 128 + e] * g_dv[d][e];
            sr += grw[j * 160 + 128 + e] * g_dv[d][e];
        }
        g_glbe[d][j] = sl;
        g_grbe[d][j] = sr;
    }

    for (int idx = t; idx < 13 * 128; idx += 256) {
        int d = idx >> 7, kj = idx & 127;
        float s = pqb[kj] + qob[kj];
        for (int e = 0; e < 32; e++) s += qow[kj * 32 + e] * g_dv[d][e];
        g_pq[d][kj >> 6][kj & 63] = s;
    }
}

__global__ void bias_fold_kernel(const float* __restrict__ glb, const float* __restrict__ grb)
{
    int t = threadIdx.x;
    for (int idx = t; idx < 13 * 64; idx += 256) {
        int d = idx >> 6, j = idx & 63;
        g_glbe[d][j] = glb[j] + g_glbe[d][j];
        g_grbe[d][j] = grb[j] + g_grbe[d][j];
    }
}

// ---------------- bf16-split tensor-core GEMM on pre-split operands ----------------
// A: g_Ah/g_Al (4096x256 uints), W: g_Wh/g_Wl (512x256 uints). Load phase is a pure copy.
// k-accumulation order identical to the round-16 kernel -> bitwise-identical results.
template <int MODE>
__global__ void __launch_bounds__(256) gemm_pre(float* __restrict__ C)
{
    __shared__ unsigned int Ah[128][20], Al[128][20], Bh[128][20], Bl[128][20];
    int t = threadIdx.x;
    int lane = t & 31, wid = t >> 5;
    int wm = (wid & 1) * 64, wn = (wid >> 1) * 32;
    int m0 = blockIdx.x * 128, n0 = blockIdx.y * 128;
    int g = lane >> 2, tq = lane & 3;

    float c[4][4][4];
#pragma unroll
    for (int i = 0; i < 4; i++)
#pragma unroll
        for (int j = 0; j < 4; j++)
#pragma unroll
            for (int k = 0; k < 4; k++) c[i][j][k] = 0.0f;

    for (int kc = 0; kc < 16; kc++) {        // 16 chunks of 32 k
        int ku4 = kc * 4;                    // uint4 col offset within row (row = 64 uint4)
#pragma unroll
        for (int p = 0; p < 2; p++) {
            int idx = t + 256 * p;           // 0..511
            int row = idx >> 2, c4 = idx & 3;
            uint4 va = *(const uint4*)(g_Ah + ((size_t)(m0 + row) * 64 + ku4 + c4) * 4);
            *(uint4*)&Ah[row][c4 * 4] = va;
            uint4 vb = *(const uint4*)(g_Al + ((size_t)(m0 + row) * 64 + ku4 + c4) * 4);
            *(uint4*)&Al[row][c4 * 4] = vb;
            uint4 vc = *(const uint4*)(g_Wh + ((size_t)(n0 + row) * 64 + ku4 + c4) * 4);
            *(uint4*)&Bh[row][c4 * 4] = vc;
            uint4 vd = *(const uint4*)(g_Wl + ((size_t)(n0 + row) * 64 + ku4 + c4) * 4);
            *(uint4*)&Bl[row][c4 * 4] = vd;
        }
        __syncthreads();

#pragma unroll
        for (int s = 0; s < 2; s++) {
            int o = s * 8;
            unsigned int ah[4][4], al[4][4], bh[4][2], bl[4][2];
#pragma unroll
            for (int mt = 0; mt < 4; mt++) {
                int r = wm + mt * 16 + g;
                ah[mt][0] = Ah[r][o + tq];     ah[mt][1] = Ah[r + 8][o + tq];
                ah[mt][2] = Ah[r][o + tq + 4]; ah[mt][3] = Ah[r + 8][o + tq + 4];
                al[mt][0] = Al[r][o + tq];     al[mt][1] = Al[r + 8][o + tq];
                al[mt][2] = Al[r][o + tq + 4]; al[mt][3] = Al[r + 8][o + tq + 4];
            }
#pragma unroll
            for (int nt = 0; nt < 4; nt++) {
                int n = wn + nt * 8 + g;
                bh[nt][0] = Bh[n][o + tq]; bh[nt][1] = Bh[n][o + tq + 4];
                bl[nt][0] = Bl[n][o + tq]; bl[nt][1] = Bl[n][o + tq + 4];
            }
#pragma unroll
            for (int mt = 0; mt < 4; mt++)
#pragma unroll
                for (int nt = 0; nt < 4; nt++) {
                    mma_bf16(c[mt][nt], ah[mt], bh[nt]);
                    mma_bf16(c[mt][nt], al[mt], bh[nt]);
                    mma_bf16(c[mt][nt], ah[mt], bl[nt]);
                }
        }
        __syncthreads();
    }

#pragma unroll
    for (int mt = 0; mt < 4; mt++)
#pragma unroll
        for (int nt = 0; nt < 4; nt++) {
            int r0 = m0 + wm + mt * 16 + g;
            int cc = n0 + wn + nt * 8 + tq * 2;
            float2 v0 = make_float2(c[mt][nt][0], c[mt][nt][1]);
            float2 v1 = make_float2(c[mt][nt][2], c[mt][nt][3]);
            if (MODE == 0) {
                *(float2*)(C + (size_t)r0 * DMODEL + cc) = v0;
                *(float2*)(C + (size_t)(r0 + 8) * DMODEL + cc) = v1;
            } else if (MODE == 2) {
                *(float2*)(g_qbase + (size_t)r0 * DMODEL + cc) = v0;
                *(float2*)(g_qbase + (size_t)(r0 + 8) * DMODEL + cc) = v1;
            } else {
                int hh = cc >> 6, dd = cc & 63;
                int b0 = r0 >> 11, l0 = r0 & 2047;
                *(float2*)(g_tree + ((size_t)(((LEAF + l0) * 2 + b0) * 8 + hh)) * 128 + dd) = v0;
                int r1 = r0 + 8;
                int b1 = r1 >> 11, l1 = r1 & 2047;
                *(float2*)(g_tree + ((size_t)(((LEAF + l1) * 2 + b1) * 8 + hh)) * 128 + dd) = v1;
            }
        }
}

// ---------------- big-level merge: 2 nodes/warp, phased, dv folded (128-dim gate loop) ----------------
template <int KC>
__global__ void __launch_bounds__(256) merge_npw2(int d, int lo,
                             const float* __restrict__ ln_g, const float* __restrict__ ln_b)
{
    constexpr int NS = 2 * KC;
    __shared__ float s_gin[8][128][4];
    int warp = threadIdx.x >> 5;
    int lane = threadIdx.x & 31;
    int grp = blockIdx.x * 8 + warp;
    if (grp >= (lo >> 1) * 8) return;
    int node0 = lo + (grp >> 3) * 2;
    int h = grp & 7;

    float pr = g_pr[d][h], pi = g_pi[d][h];

#pragma unroll
    for (int j = 0; j < 2; j++) {
        int node = node0 + j;
#pragma unroll
        for (int b = 0; b < 2; b++) {
            const float* tl = g_tree + (size_t)(((2 * node) * 2 + b) * 8 + h) * 128;
            const float* tr = g_tree + (size_t)(((2 * node + 1) * 2 + b) * 8 + h) * 128;
            float fla[KC], flb[KC], rta[KC], rtb[KC];
#pragma unroll
            for (int k = 0; k < KC; k++) {
                fla[k] = tl[k * 64 + lane];
                flb[k] = tl[k * 64 + lane + 32];
                float fr = tr[k * 64 + lane];
                float fi = tr[k * 64 + lane + 32];
                rta[k] = pr * fr - pi * fi;
                rtb[k] = pi * fr + pr * fi;
            }
            float lma, lmb, rma, rmb;
            if (KC == 2) {
                lma = 0.5f * (fla[0] + fla[1]); lmb = 0.5f * (flb[0] + flb[1]);
                rma = 0.5f * (rta[0] + rta[1]); rmb = 0.5f * (rtb[0] + rtb[1]);
            } else {
                lma = fla[0]; lmb = flb[0]; rma = rta[0]; rmb = rtb[0];
            }
            int slot = j * 2 + b;
            s_gin[warp][lane][slot] = lma;
            s_gin[warp][lane + 32][slot] = lmb;
            s_gin[warp][64 + lane][slot] = rma;
            s_gin[warp][96 + lane][slot] = rmb;
        }
    }
    __syncwarp();

    float al0[2][2], al1[2][2], ar0[2][2], ar1[2][2], ska[2][2], skb[2][2];
    {
        float bl0 = g_glbe[d][lane], bl1 = g_glbe[d][lane + 32];
        float br0 = g_grbe[d][lane], br1 = g_grbe[d][lane + 32];
#pragma unroll
        for (int j = 0; j < 2; j++)
#pragma unroll
            for (int b = 0; b < 2; b++) {
                al0[j][b] = bl0; al1[j][b] = bl1;
                ar0[j][b] = br0; ar1[j][b] = br1;
                ska[j][b] = 0.0f; skb[j][b] = 0.0f;
            }
    }
#pragma unroll 2
    for (int i = 0; i < 64; i++) {
        float4 w = g_gw[i][lane];
        float2 w2 = g_skw[i][lane];
        float4 gv = *(const float4*)&s_gin[warp][i][0];
        float gval[2][2] = {{gv.x, gv.y}, {gv.z, gv.w}};
#pragma unroll
        for (int j = 0; j < 2; j++)
#pragma unroll
            for (int b = 0; b < 2; b++) {
                float gi = gval[j][b];
                al0[j][b] = fmaf(w.x, gi, al0[j][b]); al1[j][b] = fmaf(w.y, gi, al1[j][b]);
                ar0[j][b] = fmaf(w.z, gi, ar0[j][b]); ar1[j][b] = fmaf(w.w, gi, ar1[j][b]);
                ska[j][b] = fmaf(w2.x, gi, ska[j][b]); skb[j][b] = fmaf(w2.y, gi, skb[j][b]);
            }
    }
#pragma unroll 2
    for (int i = 64; i < 128; i++) {
        float4 w = g_gw[i][lane];
        float4 gv = *(const float4*)&s_gin[warp][i][0];
        float gval[2][2] = {{gv.x, gv.y}, {gv.z, gv.w}};
#pragma unroll
        for (int j = 0; j < 2; j++)
#pragma unroll
            for (int b = 0; b < 2; b++) {
                float gi = gval[j][b];
                al0[j][b] = fmaf(w.x, gi, al0[j][b]); al1[j][b] = fmaf(w.y, gi, al1[j][b]);
                ar0[j][b] = fmaf(w.z, gi, ar0[j][b]); ar1[j][b] = fmaf(w.w, gi, ar1[j][b]);
            }
    }

    float sa = g_sigalpha;
    float gma = ln_g[lane], gmb = ln_g[lane + 32];
    float bta = ln_b[lane], btb = ln_b[lane + 32];

#pragma unroll
    for (int j = 0; j < 2; j++) {
        int node = node0 + j;
#pragma unroll
        for (int b = 0; b < 2; b++) {
            const float* tl = g_tree + (size_t)(((2 * node) * 2 + b) * 8 + h) * 128;
            const float* tr = g_tree + (size_t)(((2 * node + 1) * 2 + b) * 8 + h) * 128;
            float fla[KC], flb[KC], rta[KC], rtb[KC];
#pragma unroll
            for (int k = 0; k < KC; k++) {
                fla[k] = tl[k * 64 + lane];
                flb[k] = tl[k * 64 + lane + 32];
                float fr = tr[k * 64 + lane];
                float fi = tr[k * 64 + lane + 32];
                rta[k] = pr * fr - pi * fi;
                rtb[k] = pi * fr + pr * fi;
            }
            float gla = sigf(al0[j][b]), glv = sigf(al1[j][b]);
            float gra = sigf(ar0[j][b]), grv = sigf(ar1[j][b]);

            float bka[NS], bkb[NS];
#pragma unroll
            for (int k = 0; k < KC; k++) {
                bka[k] = fla[k] * gla;      bkb[k] = flb[k] * glv;
                bka[KC + k] = rta[k] * gra; bkb[KC + k] = rtb[k] * grv;
            }
            size_t obase = (size_t)((node * 2 + b) * 8 + h) * 128;

#pragma unroll
            for (int q = 0; q < 2; q++) {
                float pqa = g_pq[d][q][lane], pqb = g_pq[d][q][lane + 32];
                float sc[NS];
#pragma unroll
                for (int s = 0; s < NS; s++) {
                    float p = pqa * bka[s] + pqb * bkb[s];
                    sc[s] = wsum(p) * 0.125f;
                }
                float mx = sc[0];
#pragma unroll
                for (int s = 1; s < NS; s++) mx = fmaxf(mx, sc[s]);
                float den = 0.0f;
#pragma unroll
                for (int s = 0; s < NS; s++) { sc[s] = __expf(sc[s] - mx); den += sc[s]; }
                float inv = 1.0f / den;
                float ra = 0.0f, rb = 0.0f;
#pragma unroll
                for (int s = 0; s < NS; s++) {
                    float w = sc[s] * inv;
                    ra = fmaf(w, bka[s], ra);
                    rb = fmaf(w, bkb[s], rb);
                }
                float mu = wsum(ra + rb) * (1.0f / 64.0f);
                float da = ra - mu, db = rb - mu;
                float var = wsum(da * da + db * db) * (1.0f / 64.0f);
                float rstd = rsqrtf(var + 1e-5f);
                g_tree[obase + q * 64 + lane]      = da * rstd * gma + bta + sa * ska[j][b];
                g_tree[obase + q * 64 + lane + 32] = db * rstd * gmb + btb + sa * skb[j][b];
            }
        }
    }
}

// ---------------- small-level merge (dv folded, 128-dim gate loop) ----------------
template <int KC>
__global__ void merge_kernel(int d, int lo,
                             const float* __restrict__ ln_g, const float* __restrict__ ln_b)
{
    constexpr int NS = 2 * KC;
    __shared__ float s_gin[8][2][128];
    int warp = threadIdx.x >> 5;
    int lane = threadIdx.x & 31;
    int inst = blockIdx.x * 8 + warp;
    if (inst >= lo * 8) return;
    int node = lo + (inst >> 3);
    int h = inst & 7;

    float pr = g_pr[d][h], pi = g_pi[d][h];
    float fla[2][KC], flb[2][KC], rta[2][KC], rtb[2][KC];
#pragma unroll
    for (int b = 0; b < 2; b++) {
        const float* tl = g_tree + (size_t)(((2 * node) * 2 + b) * 8 + h) * 128;
        const float* tr = g_tree + (size_t)(((2 * node + 1) * 2 + b) * 8 + h) * 128;
#pragma unroll
        for (int k = 0; k < KC; k++) {
            fla[b][k] = tl[k * 64 + lane];
            flb[b][k] = tl[k * 64 + lane + 32];
            float fr = tr[k * 64 + lane];
            float fi = tr[k * 64 + lane + 32];
            rta[b][k] = pr * fr - pi * fi;
            rtb[b][k] = pi * fr + pr * fi;
        }
        float lma, lmb, rma, rmb;
        if (KC == 2) {
            lma = 0.5f * (fla[b][0] + fla[b][1]); lmb = 0.5f * (flb[b][0] + flb[b][1]);
            rma = 0.5f * (rta[b][0] + rta[b][1]); rmb = 0.5f * (rtb[b][0] + rtb[b][1]);
        } else {
            lma = fla[b][0]; lmb = flb[b][0]; rma = rta[b][0]; rmb = rtb[b][0];
        }
        float* gin = s_gin[warp][b];
        gin[lane] = lma; gin[lane + 32] = lmb;
        gin[64 + lane] = rma; gin[96 + lane] = rmb;
    }
    __syncwarp();

    float al0[2], al1[2], ar0[2], ar1[2];
#pragma unroll
    for (int b = 0; b < 2; b++) {
        al0[b] = g_glbe[d][lane]; al1[b] = g_glbe[d][lane + 32];
        ar0[b] = g_grbe[d][lane]; ar1[b] = g_grbe[d][lane + 32];
    }
#pragma unroll 4
    for (int i = 0; i < 128; i++) {
        float4 w = g_gw[i][lane];
#pragma unroll
        for (int b = 0; b < 2; b++) {
            float gi = s_gin[warp][b][i];
            al0[b] = fmaf(w.x, gi, al0[b]); al1[b] = fmaf(w.y, gi, al1[b]);
            ar0[b] = fmaf(w.z, gi, ar0[b]); ar1[b] = fmaf(w.w, gi, ar1[b]);
        }
    }

    float ska[2], skb[2];
    ska[0] = ska[1] = skb[0] = skb[1] = 0.0f;
#pragma unroll 4
    for (int i = 0; i < 64; i++) {
        float2 w = g_skw[i][lane];
#pragma unroll
        for (int b = 0; b < 2; b++) {
            float l = s_gin[warp][b][i];
            ska[b] = fmaf(w.x, l, ska[b]);
            skb[b] = fmaf(w.y, l, skb[b]);
        }
    }

    float sa = g_sigalpha;
    float gma = ln_g[lane], gmb = ln_g[lane + 32];
    float bta = ln_b[lane], btb = ln_b[lane + 32];

#pragma unroll
    for (int b = 0; b < 2; b++) {
        float gla = sigf(al0[b]), glv = sigf(al1[b]);
        float gra = sigf(ar0[b]), grv = sigf(ar1[b]);

        float bka[NS], bkb[NS];
#pragma unroll
        for (int k = 0; k < KC; k++) {
            bka[k] = fla[b][k] * gla;      bkb[k] = flb[b][k] * glv;
            bka[KC + k] = rta[b][k] * gra; bkb[KC + k] = rtb[b][k] * grv;
        }
        size_t obase = (size_t)((node * 2 + b) * 8 + h) * 128;

#pragma unroll
        for (int q = 0; q < 2; q++) {
            float pqa = g_pq[d][q][lane], pqb = g_pq[d][q][lane + 32];
            float sc[NS];
#pragma unroll
            for (int s = 0; s < NS; s++) {
                float p = pqa * bka[s] + pqb * bkb[s];
                sc[s] = wsum(p) * 0.125f;
            }
            float mx = sc[0];
#pragma unroll
            for (int s = 1; s < NS; s++) mx = fmaxf(mx, sc[s]);
            float den = 0.0f;
#pragma unroll
            for (int s = 0; s < NS; s++) { sc[s] = __expf(sc[s] - mx); den += sc[s]; }
            float inv = 1.0f / den;
            float ra = 0.0f, rb = 0.0f;
#pragma unroll
            for (int s = 0; s < NS; s++) {
                float w = sc[s] * inv;
                ra = fmaf(w, bka[s], ra);
                rb = fmaf(w, bkb[s], rb);
            }
            float mu = wsum(ra + rb) * (1.0f / 64.0f);
            float da = ra - mu, db = rb - mu;
            float var = wsum(da * da + db * db) * (1.0f / 64.0f);
            float rstd = rsqrtf(var + 1e-5f);
            g_tree[obase + q * 64 + lane]      = da * rstd * gma + bta + sa * ska[b];
            g_tree[obase + q * 64 + lane + 32] = db * rstd * gmb + btb + sa * skb[b];
        }
    }
}

// ---------------- u = W_s^T v for the 2048 cover-reachable (node,depth) entries ----------------
__global__ void utransform_kernel(const float* __restrict__ dpw)
{
    __shared__ float sv[8][4][64];
    int e = blockIdx.x;                    // 0..2047
    int h = threadIdx.x >> 5, lane = threadIdx.x & 31;

    int s = 0, base = 0;
#pragma unroll
    for (int ss = 0; ss < 12; ss++) {
        int cnt = 1024 >> ss; if (cnt == 0) cnt = 1;
        if (e >= base + cnt) { base += cnt; s = ss + 1; }
        else break;
    }
    int node = (1 << (12 - s)) + 2 * (e - base);
    int kv = (s == 0) ? 1 : 2;
    int nvec = 2 * kv;
    const float* W = dpw + (size_t)s * 4096;

    for (int j = 0; j < nvec; j++) {
        int b = j / kv, k = j % kv;
        const float* src = g_tree + (size_t)((node * 2 + b) * 8 + h) * 128 + k * 64;
        sv[h][j][lane] = src[lane];
        sv[h][j][lane + 32] = src[lane + 32];
    }
    __syncwarp();

    float u0[4] = {0, 0, 0, 0}, u1[4] = {0, 0, 0, 0};
    for (int o = 0; o < 64; o++) {
        float w0 = W[o * 64 + lane];
        float w1 = W[o * 64 + lane + 32];
#pragma unroll
        for (int j = 0; j < 4; j++) {
            if (j < nvec) {
                float v = sv[h][j][o];
                u0[j] = fmaf(w0, v, u0[j]);
                u1[j] = fmaf(w1, v, u1[j]);
            }
        }
    }
    for (int j = 0; j < nvec; j++) {
        int b = j / kv, k = j % kv;
        float* dst = g_u + (size_t)((node * 2 + b) * 8 + h) * 128 + k * 64;
        dst[lane] = u0[j];
        dst[lane + 32] = u1[j];
    }
}

// ---------------- cover attention: one warp per (t,b,h), scores use q.(v+u) ----------------
__global__ void cover_attn_kernel()
{
    int t = blockIdx.x, b = blockIdx.y;
    int h = threadIdx.x >> 5, lane = threadIdx.x & 31;
    int pos = t + 1;
    const float* qp = g_qbase + (size_t)(b * LL + t) * DMODEL + h * 64;
    float qa = qp[lane], qb = qp[lane + 32];

    float m = -1e30f, den = 0.0f, ca = 0.0f, cb = 0.0f;
#pragma unroll
    for (int s = 0; s < 12; s++) {
        if ((pos >> s) & 1) {
            int node = ((LEAF + pos) >> s) - 1;
            float scl = g_scale[s];
            size_t off = (size_t)((node * 2 + b) * 8 + h) * 128;
            int kv = (s == 0) ? 1 : 2;
            for (int k = 0; k < kv; k++) {
                float va = g_tree[off + k * 64 + lane];
                float vb = g_tree[off + k * 64 + lane + 32];
                float ua = g_u[off + k * 64 + lane];
                float ub = g_u[off + k * 64 + lane + 32];
                float dot = wsum(qa * (va + ua) + qb * (vb + ub)) * scl;
                float nm = fmaxf(m, dot);
                float f = __expf(m - nm);
                float e = __expf(dot - nm);
                den = den * f + e;
                ca = ca * f + e * va;
                cb = cb * f + e * vb;
                m = nm;
            }
        }
    }
    float inv = 1.0f / den;
    size_t o = (size_t)(b * LL + t) * DMODEL + h * 64;
    g_ctx[o + lane] = ca * inv;
    g_ctx[o + lane + 32] = cb * inv;
}

// ---------------- launcher ----------------
extern "C" void kernel_launch(void* const* d_in, const int* in_sizes, int n_in,
                              void* d_out, int out_size)
{
    const float* x      = (const float*)d_in[0];
    const float* Wq     = (const float*)d_in[1];
    const float* Wv     = (const float*)d_in[2];
    const float* Wo     = (const float*)d_in[3];
    const float* glw    = (const float*)d_in[4];
    const float* glb    = (const float*)d_in[5];
    const float* grw    = (const float*)d_in[6];
    const float* grb    = (const float*)d_in[7];
    const float* pqb    = (const float*)d_in[8];
    const float* qow    = (const float*)d_in[9];
    const float* qob    = (const float*)d_in[10];
    const float* lng    = (const float*)d_in[11];
    const float* lnb    = (const float*)d_in[12];
    const float* skw    = (const float*)d_in[13];
    const float* salpha = (const float*)d_in[14];
    const float* wfreq  = (const float*)d_in[15];
    const float* wdamp  = (const float*)d_in[16];
    const float* wphase = (const float*)d_in[17];
    const float* dpw    = (const float*)d_in[18];
    const float* dtemp  = (const float*)d_in[19];

    unsigned int* dAh; cudaGetSymbolAddress((void**)&dAh, g_Ah);
    unsigned int* dAl; cudaGetSymbolAddress((void**)&dAl, g_Al);
    unsigned int* dWh; cudaGetSymbolAddress((void**)&dWh, g_Wh);
    unsigned int* dWl; cudaGetSymbolAddress((void**)&dWl, g_Wl);

    precompute_kernel<<<1, 256>>>(glw, grw, pqb, qow, qob, skw, salpha,
                                  wfreq, wdamp, wphase, dtemp);
    bias_fold_kernel<<<1, 256>>>(glb, grb);

    // pre-split x once (A for both Wq and Wv GEMMs)
    presplit_kernel<<<4096, 256>>>(x, dAh, dAl, 4096 * 256);

    // q_base = x @ Wq^T
    presplit_kernel<<<512, 256>>>(Wq, dWh, dWl, 512 * 256);
    gemm_pre<2><<<dim3(32, 4), 256>>>(nullptr);

    // v -> tree leaves = x @ Wv^T
    presplit_kernel<<<512, 256>>>(Wv, dWh, dWl, 512 * 256);
    gemm_pre<1><<<dim3(32, 4), 256>>>(nullptr);

    // tree merges, levels 1..11 (root unused by covers)
    for (int d = 1; d <= 11; d++) {
        int lo = 1 << (12 - d);
        if (d == 1) {
            merge_npw2<1><<<lo / 2, 256>>>(d, lo, lng, lnb);
        } else if (lo >= 256) {          // d = 2..4
            merge_npw2<2><<<lo / 2, 256>>>(d, lo, lng, lnb);
        } else {
            merge_kernel<2><<<lo, 256>>>(d, lo, lng, lnb);
        }
    }

    // u = W_s^T v on cover-reachable nodes
    utransform_kernel<<<2048, 256>>>(dpw);

    // cover attention -> ctx
    cover_attn_kernel<<<dim3(LL, BB), 256>>>();

    // out = ctx @ Wo^T
    presplit_ctx_kernel<<<4096, 256>>>();
    presplit_kernel<<<512, 256>>>(Wo, dWh, dWl, 512 * 256);
    gemm_pre<0><<<dim3(32, 4), 256>>>((float*)d_out);
}